// round 11
// baseline (speedup 1.0000x reference)
#include <cuda_runtime.h>
#include <cuda_bf16.h>
#include <math.h>

#define NTOK (32768*16)          // 524288 tokens
#define TPB  256
#define TOKS 64                  // tokens per tile
#define NT   4                   // tiles per CTA
#define NBLK (NTOK/(TOKS*NT))    // 2048 CTAs

// ---------------- device globals (allocation-free scratch) ----------------
__device__ float g_scratch[(size_t)NTOK * 64];
__device__ __align__(16) __nv_bfloat16 g_W1b[64*256];
__device__ __align__(16) __nv_bfloat16 g_W2b[256*64];
__device__ __align__(16) __nv_bfloat16 g_Tu[64*192];   // [d][h*8+s (+0/64/128 for q/k/v)]
__device__ __align__(16) __nv_bfloat16 g_Tm[64*192];
__device__ __align__(16) __nv_bfloat16 g_Wpu[64*64];
__device__ __align__(16) __nv_bfloat16 g_Wpm[64*64];

// ---------------- small helpers ----------------
__device__ __forceinline__ unsigned bf2u(float a, float b) {
    unsigned r;
    asm("cvt.rn.bf16x2.f32 %0, %1, %2;" : "=r"(r) : "f"(b), "f"(a));
    return r;
}
__device__ __forceinline__ unsigned su32(const void* p) {
    return (unsigned)__cvta_generic_to_shared(p);
}
// fast GELU: 0.5z(1+tanh(0.79788456(z + 0.044715 z^3))), HW tanh
__device__ __forceinline__ float gelu_f(float z) {
    float w = z * fmaf(0.035677408136f, z*z, 0.79788456080287f);
    float t;
    asm("tanh.approx.f32 %0, %1;" : "=f"(t) : "f"(w));
    float hz = 0.5f*z;
    return fmaf(hz, t, hz);
}

#define LDSM2(r0,r1,addr) \
    asm volatile("ldmatrix.sync.aligned.m8n8.x2.shared.b16 {%0,%1},[%2];" \
        : "=r"(r0),"=r"(r1) : "r"(addr))
#define LDSM2T(r0,r1,addr) \
    asm volatile("ldmatrix.sync.aligned.m8n8.x2.trans.shared.b16 {%0,%1},[%2];" \
        : "=r"(r0),"=r"(r1) : "r"(addr))
#define LDSM4(r0,r1,r2,r3,addr) \
    asm volatile("ldmatrix.sync.aligned.m8n8.x4.shared.b16 {%0,%1,%2,%3},[%4];" \
        : "=r"(r0),"=r"(r1),"=r"(r2),"=r"(r3) : "r"(addr))
#define LDSM4T(r0,r1,r2,r3,addr) \
    asm volatile("ldmatrix.sync.aligned.m8n8.x4.trans.shared.b16 {%0,%1,%2,%3},[%4];" \
        : "=r"(r0),"=r"(r1),"=r"(r2),"=r"(r3) : "r"(addr))
#define MMA16816(c0,c1,c2,c3,a0,a1,a2,a3,b0,b1) \
    asm volatile("mma.sync.aligned.m16n8k16.row.col.f32.bf16.bf16.f32 " \
        "{%0,%1,%2,%3},{%4,%5,%6,%7},{%8,%9},{%0,%1,%2,%3};" \
        : "+f"(c0),"+f"(c1),"+f"(c2),"+f"(c3) \
        : "r"(a0),"r"(a1),"r"(a2),"r"(a3),"r"(b0),"r"(b1))
#define MMA16808(c0,c1,c2,c3,a0,a1,b0) \
    asm volatile("mma.sync.aligned.m16n8k8.row.col.f32.bf16.bf16.f32 " \
        "{%0,%1,%2,%3},{%4,%5},{%6},{%0,%1,%2,%3};" \
        : "+f"(c0),"+f"(c1),"+f"(c2),"+f"(c3) \
        : "r"(a0),"r"(a1),"r"(b0))

// ---- LN split into prefetch (LDG only) + commit (shuffle + STS) ----
__device__ __forceinline__ void ln_prefetch(float* xv, const float* __restrict__ xin,
                                            size_t base, int tid) {
    const int t = tid >> 2, qp = tid & 3;
    const float4* x4 = (const float4*)(xin + (base + t)*64) + qp*4;
#pragma unroll
    for (int i = 0; i < 4; i++) {
        float4 v = x4[i];
        xv[4*i]=v.x; xv[4*i+1]=v.y; xv[4*i+2]=v.z; xv[4*i+3]=v.w;
    }
}
__device__ __forceinline__ void ln_commit(const float* xv, char* __restrict__ sA,
                                          int tid, const float* __restrict__ sg) {
    const int t = tid >> 2, qp = tid & 3;
    float s = 0.f, ss = 0.f;
#pragma unroll
    for (int i = 0; i < 16; i++) { s += xv[i]; ss = fmaf(xv[i], xv[i], ss); }
    s  += __shfl_xor_sync(0xffffffffu, s, 1);  ss += __shfl_xor_sync(0xffffffffu, ss, 1);
    s  += __shfl_xor_sync(0xffffffffu, s, 2);  ss += __shfl_xor_sync(0xffffffffu, ss, 2);
    const float mean = s * (1.f/64.f);
    const float var  = ss * (1.f/64.f) - mean*mean;
    const float rstd = rsqrtf(var + 1e-5f);
    const int kb = qp * 16;
#pragma unroll
    for (int c = 0; c < 2; c++) {
        float v[8];
#pragma unroll
        for (int e = 0; e < 8; e++) {
            int k = kb + c*8 + e;
            v[e] = (xv[c*8+e] - mean) * rstd * sg[k] + sg[64+k];
        }
        uint4 q;
        q.x = bf2u(v[0], v[1]); q.y = bf2u(v[2], v[3]);
        q.z = bf2u(v[4], v[5]); q.w = bf2u(v[6], v[7]);
        int ch = qp*2 + c;
        *(uint4*)(sA + t*128 + ((ch ^ (t & 7)) << 4)) = q;
    }
}

// ---------------- prep: fp32 weights -> bf16 (and qkv transpose) ----------------
__global__ void prep_kernel(const float* __restrict__ W1, const float* __restrict__ W2,
                            const float* __restrict__ uWq, const float* __restrict__ uWk,
                            const float* __restrict__ uWv, const float* __restrict__ uWp,
                            const float* __restrict__ mWq, const float* __restrict__ mWk,
                            const float* __restrict__ mWv, const float* __restrict__ mWp)
{
    int i0 = blockIdx.x * blockDim.x + threadIdx.x;
    int stride = gridDim.x * blockDim.x;
    for (int i = i0; i < 16384; i += stride) {
        g_W1b[i] = __float2bfloat16(W1[i]);
        g_W2b[i] = __float2bfloat16(W2[i]);
    }
    for (int i = i0; i < 4096; i += stride) {
        int h = i >> 9, d = (i >> 3) & 63, s = i & 7;
        int c = h*8 + s;
        g_Tu[d*192 + c]       = __float2bfloat16(uWq[i]);
        g_Tu[d*192 + 64 + c]  = __float2bfloat16(uWk[i]);
        g_Tu[d*192 + 128 + c] = __float2bfloat16(uWv[i]);
        g_Tm[d*192 + c]       = __float2bfloat16(mWq[i]);
        g_Tm[d*192 + 64 + c]  = __float2bfloat16(mWk[i]);
        g_Tm[d*192 + 128 + c] = __float2bfloat16(mWv[i]);
        g_Wpu[i] = __float2bfloat16(uWp[i]);
        g_Wpm[i] = __float2bfloat16(mWp[i]);
    }
}

// ==================================================================
// FFN kernel: out = x + gelu(LN(x)@W1 + b1)@W2 + b2 ; NT tiles/CTA
// phase1: warp = 32 tokens x 64 hidden (tg = wid&1, jg = wid>>1);
// phase2: 4-way k-split (k-slab 64/warp) over all n=64;
// reduction: 2-round balanced tree (jg^1 halves, then jg^2 quarters).
// Single sA (LN committed between reduction barriers).
// ==================================================================
#define FFN_SW1  0
#define FFN_SW2  32768
#define FFN_SA   65536
#define FFN_SRED 73728            // 4 regions x 32 rows x 68 floats = 34816 B
#define FFN_SB1  108544
#define FFN_SB2  109568
#define FFN_SG   109824
#define FFN_SMEM_BYTES 110336

__global__ void __launch_bounds__(TPB, 2) ffn_kernel(
    const float* __restrict__ xin, float* __restrict__ xout,
    const float* __restrict__ b1, const float* __restrict__ b2,
    const float* __restrict__ g2, const float* __restrict__ be2)
{
    extern __shared__ char smc[];
    float* sb1 = (float*)(smc + FFN_SB1);
    float* sb2 = (float*)(smc + FFN_SB2);
    float* sg  = (float*)(smc + FFN_SG);

    const int tid = threadIdx.x;
    const unsigned sbase = su32(smc);

    {
        const uint4* src1 = (const uint4*)g_W1b;
        const uint4* src2 = (const uint4*)g_W2b;
        for (int c = tid; c < 2048; c += TPB) {
            int r1 = c >> 5, c1 = c & 31;
            *(uint4*)(smc + FFN_SW1 + r1*512 + ((c1 ^ (r1 & 7)) << 4)) = src1[c];
            int r2 = c >> 3, c2 = c & 7;
            *(uint4*)(smc + FFN_SW2 + r2*128 + ((c2 ^ (r2 & 7)) << 4)) = src2[c];
        }
    }
    sb1[tid] = b1[tid];
    if (tid < 64) { sb2[tid] = b2[tid]; sg[tid] = g2[tid]; sg[64+tid] = be2[tid]; }
    __syncthreads();

    const int lane = tid & 31, wid = tid >> 5;
    const int gid = lane >> 2, tig = lane & 3;
    const int tg = wid & 1, jg = wid >> 1;    // tokens [tg*32,+32), hidden [jg*64,+64)
    const int jb = jg * 64;
    // reduction constants
    const int q     = ((jg & 1) << 1) | (jg >> 1);  // finalized n-quarter
    const int r1fin = (jg & 1) * 4;                  // round-1 finalize m base
    const int r1sto = 4 - r1fin;                     // round-1 stored   m base
    const int r2fin = q * 2;                         // round-2 finalize m base
    const int r2sto = (q ^ 1) * 2;                   // round-2 stored   m base
    float* r1buf = (float*)(smc + FFN_SRED) + (tg*2 + (jg>>1)) * (32*68);
    float* r2buf = (float*)(smc + FFN_SRED) + tg * (32*68);

    const size_t cta0 = (size_t)blockIdx.x * NT * TOKS;

    float xv[16];
    ln_prefetch(xv, xin, cta0, tid);
    ln_commit(xv, smc + FFN_SA, tid, sg);
    __syncthreads();

    for (int tt = 0; tt < NT; tt++) {
        const size_t base = cta0 + (size_t)tt * TOKS;

        // ---------- phase 1: Z = A @ W1 ; warp = 32t x 64j ----------
        float acc[2][8][4];
#pragma unroll
        for (int mi = 0; mi < 2; mi++)
#pragma unroll
            for (int m = 0; m < 8; m++)
#pragma unroll
                for (int p = 0; p < 4; p++) acc[mi][m][p] = 0.f;

#pragma unroll
        for (int ks = 0; ks < 4; ks++) {
            const int k0 = ks * 16;
            unsigned aA[2][4];
#pragma unroll
            for (int mi = 0; mi < 2; mi++) {
                int ar = tg*32 + mi*16 + (lane & 15);
                int ac = (k0 >> 3) + (lane >> 4);
                unsigned aaddr = sbase + FFN_SA + ar*128 + ((ac ^ (ar & 7)) << 4);
                LDSM4(aA[mi][0], aA[mi][1], aA[mi][2], aA[mi][3], aaddr);
            }
#pragma unroll
            for (int st = 0; st < 4; st++) {
                int n0 = jb + st * 16;
                unsigned b0,b1r,b2,b3;
                int br = k0 + (lane & 15);
                int bc = (n0 >> 3) + (lane >> 4);
                unsigned baddr = sbase + FFN_SW1 + br*512 + ((bc ^ (br & 7)) << 4);
                LDSM4T(b0,b1r,b2,b3, baddr);
#pragma unroll
                for (int mi = 0; mi < 2; mi++) {
                    MMA16816(acc[mi][2*st][0],acc[mi][2*st][1],acc[mi][2*st][2],acc[mi][2*st][3],
                             aA[mi][0],aA[mi][1],aA[mi][2],aA[mi][3], b0,b1r);
                    MMA16816(acc[mi][2*st+1][0],acc[mi][2*st+1][1],acc[mi][2*st+1][2],acc[mi][2*st+1][3],
                             aA[mi][0],aA[mi][1],aA[mi][2],aA[mi][3], b2,b3);
                }
            }
        }

        // ---------- gelu in registers, pack to A-frags for phase 2 ----------
        unsigned pk[4][2][4];
#pragma unroll
        for (int mi = 0; mi < 2; mi++)
#pragma unroll
            for (int nf = 0; nf < 8; nf++) {
                int col = jb + nf*8 + 2*tig;
                float bb0 = sb1[col], bb1 = sb1[col+1];
                float h00 = gelu_f(acc[mi][nf][0] + bb0);
                float h01 = gelu_f(acc[mi][nf][1] + bb1);
                float h10 = gelu_f(acc[mi][nf][2] + bb0);
                float h11 = gelu_f(acc[mi][nf][3] + bb1);
                int kc = nf >> 1, lohi = nf & 1;
                pk[kc][mi][lohi*2 + 0] = bf2u(h00, h01);   // row gid
                pk[kc][mi][lohi*2 + 1] = bf2u(h10, h11);   // row gid+8
            }

        // prefetch next tile's x
        if (tt + 1 < NT) ln_prefetch(xv, xin, base + TOKS, tid);

        // ---------- phase 2: partial out = H_slab @ W2[jb:+64][0:64] ----------
        float acc2[2][8][4];
#pragma unroll
        for (int mi = 0; mi < 2; mi++)
#pragma unroll
            for (int m = 0; m < 8; m++)
#pragma unroll
                for (int p = 0; p < 4; p++) acc2[mi][m][p] = 0.f;

#pragma unroll
        for (int kc = 0; kc < 4; kc++) {
            const int br = jb + kc*16 + (lane & 15);
#pragma unroll
            for (int st = 0; st < 4; st++) {
                unsigned b0,b1r,b2,b3;
                int bc = st*2 + (lane >> 4);
                unsigned baddr = sbase + FFN_SW2 + br*128 + ((bc ^ (br & 7)) << 4);
                LDSM4T(b0,b1r,b2,b3, baddr);
#pragma unroll
                for (int mi = 0; mi < 2; mi++) {
                    MMA16816(acc2[mi][2*st][0],acc2[mi][2*st][1],acc2[mi][2*st][2],acc2[mi][2*st][3],
                             pk[kc][mi][0],pk[kc][mi][1],pk[kc][mi][2],pk[kc][mi][3], b0,b1r);
                    MMA16816(acc2[mi][2*st+1][0],acc2[mi][2*st+1][1],acc2[mi][2*st+1][2],acc2[mi][2*st+1][3],
                             pk[kc][mi][0],pk[kc][mi][1],pk[kc][mi][2],pk[kc][mi][3], b2,b3);
                }
            }
        }

        // ---------- round 1: exchange halves with partner jg^1 ----------
#pragma unroll
        for (int mm = 0; mm < 4; mm++) {
            int m = r1sto + mm;
            int col = (m >> 1)*16 + (m & 1)*8 + 2*tig;
#pragma unroll
            for (int mi = 0; mi < 2; mi++)
#pragma unroll
                for (int rp = 0; rp < 2; rp++) {
                    int row = mi*16 + gid + rp*8;
                    *(float2*)(r1buf + row*68 + col) =
                        make_float2(acc2[mi][m][2*rp], acc2[mi][m][2*rp+1]);
                }
        }
        __syncthreads();
#pragma unroll
        for (int mm = 0; mm < 4; mm++) {
            int m = r1fin + mm;
            int col = (m >> 1)*16 + (m & 1)*8 + 2*tig;
#pragma unroll
            for (int mi = 0; mi < 2; mi++)
#pragma unroll
                for (int rp = 0; rp < 2; rp++) {
                    int row = mi*16 + gid + rp*8;
                    float2 v = *(const float2*)(r1buf + row*68 + col);
                    acc2[mi][m][2*rp]   += v.x;
                    acc2[mi][m][2*rp+1] += v.y;
                }
        }
        // commit LN of next tile (phase 1 is long done for all warps)
        if (tt + 1 < NT) ln_commit(xv, smc + FFN_SA, tid, sg);
        __syncthreads();

        // ---------- round 2: exchange quarters with partner jg^2 ----------
#pragma unroll
        for (int mm = 0; mm < 2; mm++) {
            int m = r2sto + mm;
            int col = (m >> 1)*16 + (m & 1)*8 + 2*tig;
#pragma unroll
            for (int mi = 0; mi < 2; mi++)
#pragma unroll
                for (int rp = 0; rp < 2; rp++) {
                    int row = mi*16 + gid + rp*8;
                    *(float2*)(r2buf + row*68 + col) =
                        make_float2(acc2[mi][m][2*rp], acc2[mi][m][2*rp+1]);
                }
        }
        __syncthreads();
#pragma unroll
        for (int mm = 0; mm < 2; mm++) {
            int m = r2fin + mm;
            int e = (m >> 1)*16 + (m & 1)*8 + 2*tig;
            float bb0 = sb2[e], bb1 = sb2[e+1];
#pragma unroll
            for (int mi = 0; mi < 2; mi++)
#pragma unroll
                for (int rp = 0; rp < 2; rp++) {
                    int row = mi*16 + gid + rp*8;
                    float2 v = *(const float2*)(r2buf + row*68 + e);
                    size_t tok = base + tg*32 + row;
                    float2 x = *(const float2*)(xin + tok*64 + e);
                    float2 o = make_float2(x.x + acc2[mi][m][0 + 2*rp] + v.x + bb0,
                                           x.y + acc2[mi][m][1 + 2*rp] + v.y + bb1);
                    *(float2*)(xout + tok*64 + e) = o;
                }
        }
        __syncthreads();   // end of tile: protects SRED + sA for next iteration
    }
}

// ==================================================================
// Attention kernel (unchanged from R10): out = x + attn(LN(x))
// ==================================================================
#define ATT_ST    0
#define ATT_SWP   24576
#define ATT_SA0   32768
#define ATT_SA1   40960
#define ATT_SOB   49152
#define ATT_SQKV  57344
#define ATT_SBQKV 81920
#define ATT_SBP   82688
#define ATT_SG    82944
#define ATT_SMEM_BYTES 83456

template <bool CAUSAL>
__global__ void __launch_bounds__(TPB, 2) attn_kernel(
    const float* __restrict__ xin, float* __restrict__ xout,
    const __nv_bfloat16* __restrict__ Tqkv, const __nv_bfloat16* __restrict__ Wpb,
    const float* __restrict__ bq, const float* __restrict__ bk,
    const float* __restrict__ bv, const float* __restrict__ bp,
    const float* __restrict__ g1, const float* __restrict__ be1)
{
    extern __shared__ char smc[];
    float* sbqkv = (float*)(smc + ATT_SBQKV);
    float* sbp   = (float*)(smc + ATT_SBP);
    float* sg    = (float*)(smc + ATT_SG);

    const int tid = threadIdx.x;
    const unsigned sbase = su32(smc);

    {
        const uint4* srcT = (const uint4*)Tqkv;   // 64 rows x 24 chunks
        for (int c = tid; c < 1536; c += TPB) {
            int r = c / 24, ch = c % 24;
            *(uint4*)(smc + ATT_ST + r*384 + ((ch ^ (r & 7)) << 4)) = srcT[c];
        }
        const uint4* srcP = (const uint4*)Wpb;
        for (int c = tid; c < 512; c += TPB) {
            int r = c >> 3, ch = c & 7;
            *(uint4*)(smc + ATT_SWP + r*128 + ((ch ^ (r & 7)) << 4)) = srcP[c];
        }
    }
    if (tid < 192) sbqkv[tid] = (tid < 64) ? bq[tid] : (tid < 128 ? bk[tid-64] : bv[tid-128]);
    if (tid < 64)  sbp[tid] = bp[tid];
    if (tid < 128) sg[tid] = (tid < 64) ? g1[tid] : be1[tid-64];
    __syncthreads();

    const int lane = tid & 31, wid = tid >> 5;
    const int gid = lane >> 2, tig = lane & 3;
    const int tw = wid & 3, nh = wid >> 2;    // phase-3 mapping
    const int t0 = tw * 16;
    const int tg = wid & 1, cg = wid >> 1;    // phase-1 mapping: 32t x 48c
    const int tb0 = tg * 32;

    const size_t cta0 = (size_t)blockIdx.x * NT * TOKS;

    float xv[16];
    ln_prefetch(xv, xin, cta0, tid);
    ln_commit(xv, smc + ATT_SA0, tid, sg);
    __syncthreads();

    for (int tt = 0; tt < NT; tt++) {
        const size_t base = cta0 + (size_t)tt * TOKS;
        const unsigned curA = sbase + (((tt & 1) == 0) ? ATT_SA0 : ATT_SA1);
        const unsigned nxtOff = (((tt & 1) == 0) ? ATT_SA1 : ATT_SA0);

        // ---------- phase 1: QKV = A @ T + b ; warp = 32t x 48c ----------
        {
            float acc[2][6][4];
#pragma unroll
            for (int mi = 0; mi < 2; mi++)
#pragma unroll
                for (int m = 0; m < 6; m++)
#pragma unroll
                    for (int p = 0; p < 4; p++) acc[mi][m][p] = 0.f;

#pragma unroll
            for (int ks = 0; ks < 4; ks++) {
                const int k0 = ks * 16;
                unsigned aA[2][4];
#pragma unroll
                for (int mi = 0; mi < 2; mi++) {
                    int ar = tb0 + mi*16 + (lane & 15);
                    int ac = (k0 >> 3) + (lane >> 4);
                    unsigned aaddr = curA + ar*128 + ((ac ^ (ar & 7)) << 4);
                    LDSM4(aA[mi][0], aA[mi][1], aA[mi][2], aA[mi][3], aaddr);
                }
#pragma unroll
                for (int st = 0; st < 3; st++) {
                    int n0 = cg*48 + st * 16;
                    unsigned b0,b1r,b2,b3;
                    int br = k0 + (lane & 15);
                    int bc = (n0 >> 3) + (lane >> 4);
                    unsigned baddr = sbase + ATT_ST + br*384 + ((bc ^ (br & 7)) << 4);
                    LDSM4T(b0,b1r,b2,b3, baddr);
#pragma unroll
                    for (int mi = 0; mi < 2; mi++) {
                        MMA16816(acc[mi][2*st][0],acc[mi][2*st][1],acc[mi][2*st][2],acc[mi][2*st][3],
                                 aA[mi][0],aA[mi][1],aA[mi][2],aA[mi][3], b0,b1r);
                        MMA16816(acc[mi][2*st+1][0],acc[mi][2*st+1][1],acc[mi][2*st+1][2],acc[mi][2*st+1][3],
                                 aA[mi][0],aA[mi][1],aA[mi][2],aA[mi][3], b2,b3);
                    }
                }
            }

            if (tt + 1 < NT) ln_prefetch(xv, xin, base + TOKS, tid);

#pragma unroll
            for (int mi = 0; mi < 2; mi++)
#pragma unroll
                for (int nf = 0; nf < 6; nf++) {
                    int cc = cg*48 + nf*8;
                    int sec = cc >> 6;               // 0=q 1=k 2=v
                    int h = (cc >> 3) & 7;
                    int c = cc + 2*tig;
                    int b_loc = tg*2 + mi;
                    float bb0 = sbqkv[c], bb1 = sbqkv[c+1];
                    float scale = (sec == 0) ? 0.35355339059327373f : 1.f;
                    float v00 = (acc[mi][nf][0] + bb0) * scale, v01 = (acc[mi][nf][1] + bb1) * scale;
                    float v10 = (acc[mi][nf][2] + bb0) * scale, v11 = (acc[mi][nf][3] + bb1) * scale;
                    unsigned tb = ATT_SQKV + sec*8192 + (b_loc*8 + h)*256 + tig*4;
                    *(unsigned*)(smc + tb + gid*16)     = bf2u(v00, v01);
                    *(unsigned*)(smc + tb + (gid+8)*16) = bf2u(v10, v11);
                }
        }
        __syncthreads();

        // ---------- phase 2: MMA attention core ----------
        {
#pragma unroll
            for (int i = 0; i < 4; i++) {
                const int p = wid*4 + i;
                const int b = p >> 3, h = p & 7;
                const unsigned tq = sbase + ATT_SQKV + (b*8+h)*256 + (lane & 15)*16;

                unsigned qa0, qa1, kb0, kb1, vb0, vb1;
                LDSM2 (qa0, qa1, tq);
                LDSM2 (kb0, kb1, tq + 8192);
                LDSM2T(vb0, vb1, tq + 16384);

                float s0=0,s1=0,s2=0,s3=0,s4=0,s5=0,s6=0,s7=0;
                MMA16808(s0,s1,s2,s3, qa0,qa1, kb0);
                MMA16808(s4,s5,s6,s7, qa0,qa1, kb1);

                if (CAUSAL) {
                    const int u0 = 2*tig, u1 = 2*tig+1, u2 = 2*tig+8, u3 = 2*tig+9;
                    if (u0 > gid)   s0 = -1e30f;
                    if (u1 > gid)   s1 = -1e30f;
                    if (u2 > gid)   s4 = -1e30f;
                    if (u3 > gid)   s5 = -1e30f;
                    if (u0 > gid+8) s2 = -1e30f;
                    if (u1 > gid+8) s3 = -1e30f;
                    if (u2 > gid+8) s6 = -1e30f;
                    if (u3 > gid+8) s7 = -1e30f;
                }
                float e0 = __expf(s0), e1 = __expf(s1);
                float e4 = __expf(s4), e5 = __expf(s5);
                float e2 = __expf(s2), e3 = __expf(s3);
                float e6 = __expf(s6), e7 = __expf(s7);
                float slo = e0+e1+e4+e5, shi = e2+e3+e6+e7;
                slo += __shfl_xor_sync(0xffffffffu, slo, 1);
                slo += __shfl_xor_sync(0xffffffffu, slo, 2);
                shi += __shfl_xor_sync(0xffffffffu, shi, 1);
                shi += __shfl_xor_sync(0xffffffffu, shi, 2);
                const float ilo = 1.f/slo, ihi = 1.f/shi;

                unsigned pa0 = bf2u(e0, e1);
                unsigned pa1 = bf2u(e2, e3);
                unsigned pa2 = bf2u(e4, e5);
                unsigned pa3 = bf2u(e6, e7);

                float o0=0,o1=0,o2=0,o3=0;
                MMA16816(o0,o1,o2,o3, pa0,pa1,pa2,pa3, vb0,vb1);
                o0 *= ilo; o1 *= ilo; o2 *= ihi; o3 *= ihi;

                const int tA = b*16 + gid, tB = tA + 8;
                const int c = h*8 + 2*tig;
                unsigned offA = ATT_SOB + tA*128 + (((c>>3) ^ (tA & 7)) << 4) + ((c & 7) << 1);
                unsigned offB = ATT_SOB + tB*128 + (((c>>3) ^ (tB & 7)) << 4) + ((c & 7) << 1);
                *(unsigned*)(smc + offA) = bf2u(o0, o1);
                *(unsigned*)(smc + offB) = bf2u(o2, o3);
            }
        }
        __syncthreads();

        // ---------- phase 3: out = x + O @ Wp + bp ; warp = 16t x 32e ----------
        {
            const int ebase = nh * 32;
            float acc[4][4];
#pragma unroll
            for (int m = 0; m < 4; m++)
#pragma unroll
                for (int p = 0; p < 4; p++) acc[m][p] = 0.f;

#pragma unroll
            for (int ks = 0; ks < 4; ks++) {
                const int k0 = ks * 16;
                unsigned a0,a1,a2,a3;
                {
                    int ar = t0 + (lane & 15);
                    int ac = (k0 >> 3) + (lane >> 4);
                    unsigned aaddr = sbase + ATT_SOB + ar*128 + ((ac ^ (ar & 7)) << 4);
                    LDSM4(a0,a1,a2,a3, aaddr);
                }
#pragma unroll
                for (int st = 0; st < 2; st++) {
                    int n0 = ebase + st * 16;
                    unsigned b0,b1r,b2,b3;
                    int br = k0 + (lane & 15);
                    int bc = (n0 >> 3) + (lane >> 4);
                    unsigned baddr = sbase + ATT_SWP + br*128 + ((bc ^ (br & 7)) << 4);
                    LDSM4T(b0,b1r,b2,b3, baddr);
                    MMA16816(acc[2*st][0],acc[2*st][1],acc[2*st][2],acc[2*st][3],
                             a0,a1,a2,a3, b0,b1r);
                    MMA16816(acc[2*st+1][0],acc[2*st+1][1],acc[2*st+1][2],acc[2*st+1][3],
                             a0,a1,a2,a3, b2,b3);
                }
            }
            const int r0 = t0 + gid, r1 = t0 + gid + 8;
#pragma unroll
            for (int m = 0; m < 4; m++) {
                int e = ebase + m*8 + 2*tig;
                float bb0 = sbp[e], bb1 = sbp[e+1];
                float2 x0 = *(const float2*)(xin + (base + r0)*64 + e);
                float2 x1 = *(const float2*)(xin + (base + r1)*64 + e);
                float2 o0 = make_float2(x0.x + acc[m][0] + bb0, x0.y + acc[m][1] + bb1);
                float2 o1 = make_float2(x1.x + acc[m][2] + bb0, x1.y + acc[m][3] + bb1);
                *(float2*)(xout + (base + r0)*64 + e) = o0;
                *(float2*)(xout + (base + r1)*64 + e) = o1;
            }
        }

        if (tt + 1 < NT) ln_commit(xv, smc + nxtOff, tid, sg);
        __syncthreads();
    }
}

// ==================================================================
// launch: prep -> attn(u) -> ffn -> attn(m, causal) -> ffn
// ==================================================================
extern "C" void kernel_launch(void* const* d_in, const int* in_sizes, int n_in,
                              void* d_out, int out_size)
{
    (void)in_sizes; (void)n_in; (void)out_size;
    const float* x   = (const float*)d_in[0];
    const float* uWq = (const float*)d_in[1];  const float* ubq = (const float*)d_in[2];
    const float* uWk = (const float*)d_in[3];  const float* ubk = (const float*)d_in[4];
    const float* uWv = (const float*)d_in[5];  const float* ubv = (const float*)d_in[6];
    const float* uWp = (const float*)d_in[7];  const float* ubp = (const float*)d_in[8];
    const float* mWq = (const float*)d_in[9];  const float* mbq = (const float*)d_in[10];
    const float* mWk = (const float*)d_in[11]; const float* mbk = (const float*)d_in[12];
    const float* mWv = (const float*)d_in[13]; const float* mbv = (const float*)d_in[14];
    const float* mWp = (const float*)d_in[15]; const float* mbp = (const float*)d_in[16];
    const float* fW1 = (const float*)d_in[17]; const float* fb1 = (const float*)d_in[18];
    const float* fW2 = (const float*)d_in[19]; const float* fb2 = (const float*)d_in[20];
    const float* g1  = (const float*)d_in[21]; const float* be1 = (const float*)d_in[22];
    const float* g2  = (const float*)d_in[23]; const float* be2 = (const float*)d_in[24];
    float* out = (float*)d_out;

    float* scratch = nullptr;
    cudaGetSymbolAddress((void**)&scratch, g_scratch);
    __nv_bfloat16 *Tu = nullptr, *Tm = nullptr, *Wpu = nullptr, *Wpm = nullptr;
    cudaGetSymbolAddress((void**)&Tu, g_Tu);
    cudaGetSymbolAddress((void**)&Tm, g_Tm);
    cudaGetSymbolAddress((void**)&Wpu, g_Wpu);
    cudaGetSymbolAddress((void**)&Wpm, g_Wpm);

    cudaFuncSetAttribute(attn_kernel<false>, cudaFuncAttributeMaxDynamicSharedMemorySize, ATT_SMEM_BYTES);
    cudaFuncSetAttribute(attn_kernel<true>,  cudaFuncAttributeMaxDynamicSharedMemorySize, ATT_SMEM_BYTES);
    cudaFuncSetAttribute(ffn_kernel,         cudaFuncAttributeMaxDynamicSharedMemorySize, FFN_SMEM_BYTES);

    prep_kernel<<<32, 256>>>(fW1, fW2, uWq, uWk, uWv, uWp, mWq, mWk, mWv, mWp);

    attn_kernel<false><<<NBLK, TPB, ATT_SMEM_BYTES>>>(x, scratch, Tu, Wpu,
        ubq, ubk, ubv, ubp, g1, be1);
    ffn_kernel<<<NBLK, TPB, FFN_SMEM_BYTES>>>(scratch, out, fb1, fb2, g2, be2);
    attn_kernel<true><<<NBLK, TPB, ATT_SMEM_BYTES>>>(out, scratch, Tm, Wpm,
        mbq, mbk, mbv, mbp, g1, be1);
    ffn_kernel<<<NBLK, TPB, FFN_SMEM_BYTES>>>(scratch, out, fb1, fb2, g2, be2);
}

// round 12
// speedup vs baseline: 1.0822x; 1.0822x over previous
#include <cuda_runtime.h>
#include <cuda_bf16.h>
#include <math.h>

#define NTOK (32768*16)          // 524288 tokens
#define TPB  256
#define TOKS 64                  // tokens per tile
#define NT   4                   // tiles per CTA
#define NBLK (NTOK/(TOKS*NT))    // 2048 CTAs

// ---------------- device globals (allocation-free scratch) ----------------
__device__ float g_scratch[(size_t)NTOK * 64];
__device__ __align__(16) __nv_bfloat16 g_W1b[64*256];
__device__ __align__(16) __nv_bfloat16 g_W2b[256*64];
__device__ __align__(16) __nv_bfloat16 g_Tu[64*192];   // [d][h*8+s (+0/64/128 for q/k/v)]
__device__ __align__(16) __nv_bfloat16 g_Tm[64*192];
__device__ __align__(16) __nv_bfloat16 g_Wpu[64*64];
__device__ __align__(16) __nv_bfloat16 g_Wpm[64*64];

// ---------------- small helpers ----------------
__device__ __forceinline__ unsigned bf2u(float a, float b) {
    unsigned r;
    asm("cvt.rn.bf16x2.f32 %0, %1, %2;" : "=r"(r) : "f"(b), "f"(a));
    return r;
}
__device__ __forceinline__ unsigned su32(const void* p) {
    return (unsigned)__cvta_generic_to_shared(p);
}
// fast GELU: 0.5z(1+tanh(0.79788456(z + 0.044715 z^3))), HW tanh
__device__ __forceinline__ float gelu_f(float z) {
    float w = z * fmaf(0.035677408136f, z*z, 0.79788456080287f);
    float t;
    asm("tanh.approx.f32 %0, %1;" : "=f"(t) : "f"(w));
    float hz = 0.5f*z;
    return fmaf(hz, t, hz);
}

#define LDSM4(r0,r1,r2,r3,addr) \
    asm volatile("ldmatrix.sync.aligned.m8n8.x4.shared.b16 {%0,%1,%2,%3},[%4];" \
        : "=r"(r0),"=r"(r1),"=r"(r2),"=r"(r3) : "r"(addr))
#define LDSM4T(r0,r1,r2,r3,addr) \
    asm volatile("ldmatrix.sync.aligned.m8n8.x4.trans.shared.b16 {%0,%1,%2,%3},[%4];" \
        : "=r"(r0),"=r"(r1),"=r"(r2),"=r"(r3) : "r"(addr))
#define MMA16816(c0,c1,c2,c3,a0,a1,a2,a3,b0,b1) \
    asm volatile("mma.sync.aligned.m16n8k16.row.col.f32.bf16.bf16.f32 " \
        "{%0,%1,%2,%3},{%4,%5,%6,%7},{%8,%9},{%0,%1,%2,%3};" \
        : "+f"(c0),"+f"(c1),"+f"(c2),"+f"(c3) \
        : "r"(a0),"r"(a1),"r"(a2),"r"(a3),"r"(b0),"r"(b1))
#define MMA16808(c0,c1,c2,c3,a0,a1,b0) \
    asm volatile("mma.sync.aligned.m16n8k8.row.col.f32.bf16.bf16.f32 " \
        "{%0,%1,%2,%3},{%4,%5},{%6},{%0,%1,%2,%3};" \
        : "+f"(c0),"+f"(c1),"+f"(c2),"+f"(c3) \
        : "r"(a0),"r"(a1),"r"(b0))

// ---- LN split into prefetch (LDG only) + commit (shuffle + STS) ----
__device__ __forceinline__ void ln_prefetch(float* xv, const float* __restrict__ xin,
                                            size_t base, int tid) {
    const int t = tid >> 2, qp = tid & 3;
    const float4* x4 = (const float4*)(xin + (base + t)*64) + qp*4;
#pragma unroll
    for (int i = 0; i < 4; i++) {
        float4 v = x4[i];
        xv[4*i]=v.x; xv[4*i+1]=v.y; xv[4*i+2]=v.z; xv[4*i+3]=v.w;
    }
}
__device__ __forceinline__ void ln_commit(const float* xv, char* __restrict__ sA,
                                          int tid, const float* __restrict__ sg) {
    const int t = tid >> 2, qp = tid & 3;
    float s = 0.f, ss = 0.f;
#pragma unroll
    for (int i = 0; i < 16; i++) { s += xv[i]; ss = fmaf(xv[i], xv[i], ss); }
    s  += __shfl_xor_sync(0xffffffffu, s, 1);  ss += __shfl_xor_sync(0xffffffffu, ss, 1);
    s  += __shfl_xor_sync(0xffffffffu, s, 2);  ss += __shfl_xor_sync(0xffffffffu, ss, 2);
    const float mean = s * (1.f/64.f);
    const float var  = ss * (1.f/64.f) - mean*mean;
    const float rstd = rsqrtf(var + 1e-5f);
    const int kb = qp * 16;
#pragma unroll
    for (int c = 0; c < 2; c++) {
        float v[8];
#pragma unroll
        for (int e = 0; e < 8; e++) {
            int k = kb + c*8 + e;
            v[e] = (xv[c*8+e] - mean) * rstd * sg[k] + sg[64+k];
        }
        uint4 q;
        q.x = bf2u(v[0], v[1]); q.y = bf2u(v[2], v[3]);
        q.z = bf2u(v[4], v[5]); q.w = bf2u(v[6], v[7]);
        int ch = qp*2 + c;
        *(uint4*)(sA + t*128 + ((ch ^ (t & 7)) << 4)) = q;
    }
}

// ---------------- prep: fp32 weights -> bf16 (and qkv transpose) ----------------
__global__ void prep_kernel(const float* __restrict__ W1, const float* __restrict__ W2,
                            const float* __restrict__ uWq, const float* __restrict__ uWk,
                            const float* __restrict__ uWv, const float* __restrict__ uWp,
                            const float* __restrict__ mWq, const float* __restrict__ mWk,
                            const float* __restrict__ mWv, const float* __restrict__ mWp)
{
    int i0 = blockIdx.x * blockDim.x + threadIdx.x;
    int stride = gridDim.x * blockDim.x;
    for (int i = i0; i < 16384; i += stride) {
        g_W1b[i] = __float2bfloat16(W1[i]);
        g_W2b[i] = __float2bfloat16(W2[i]);
    }
    for (int i = i0; i < 4096; i += stride) {
        int h = i >> 9, d = (i >> 3) & 63, s = i & 7;
        int c = h*8 + s;
        g_Tu[d*192 + c]       = __float2bfloat16(uWq[i]);
        g_Tu[d*192 + 64 + c]  = __float2bfloat16(uWk[i]);
        g_Tu[d*192 + 128 + c] = __float2bfloat16(uWv[i]);
        g_Tm[d*192 + c]       = __float2bfloat16(mWq[i]);
        g_Tm[d*192 + 64 + c]  = __float2bfloat16(mWk[i]);
        g_Tm[d*192 + 128 + c] = __float2bfloat16(mWv[i]);
        g_Wpu[i] = __float2bfloat16(uWp[i]);
        g_Wpm[i] = __float2bfloat16(mWp[i]);
    }
}

// ==================================================================
// FFN kernel (R8 proven design, verbatim): out = x + gelu(LN(x)@W1+b1)@W2+b2
// ==================================================================
#define FFN_SW1  0
#define FFN_SW2  32768
#define FFN_SA0  65536
#define FFN_SA1  73728
#define FFN_SRED 81920            // 4 groups x 16 x 68 floats = 17408
#define FFN_SB1  99328
#define FFN_SB2  100352
#define FFN_SG   100608
#define FFN_SMEM_BYTES 101120

__global__ void __launch_bounds__(TPB, 2) ffn_kernel(
    const float* __restrict__ xin, float* __restrict__ xout,
    const float* __restrict__ b1, const float* __restrict__ b2,
    const float* __restrict__ g2, const float* __restrict__ be2)
{
    extern __shared__ char smc[];
    float* sb1 = (float*)(smc + FFN_SB1);
    float* sb2 = (float*)(smc + FFN_SB2);
    float* sg  = (float*)(smc + FFN_SG);

    const int tid = threadIdx.x;
    const unsigned sbase = su32(smc);

    {
        const uint4* src1 = (const uint4*)g_W1b;
        const uint4* src2 = (const uint4*)g_W2b;
        for (int c = tid; c < 2048; c += TPB) {
            int r1 = c >> 5, c1 = c & 31;
            *(uint4*)(smc + FFN_SW1 + r1*512 + ((c1 ^ (r1 & 7)) << 4)) = src1[c];
            int r2 = c >> 3, c2 = c & 7;
            *(uint4*)(smc + FFN_SW2 + r2*128 + ((c2 ^ (r2 & 7)) << 4)) = src2[c];
        }
    }
    sb1[tid] = b1[tid];
    if (tid < 64) { sb2[tid] = b2[tid]; sg[tid] = g2[tid]; sg[64+tid] = be2[tid]; }
    __syncthreads();

    const int lane = tid & 31, wid = tid >> 5;
    const int gid = lane >> 2, tig = lane & 3;
    const int tw = wid & 3, nh = wid >> 2;
    const int t0 = tw * 16;
    const int jbase = nh * 128;

    const size_t cta0 = (size_t)blockIdx.x * NT * TOKS;

    float xv[16];
    ln_prefetch(xv, xin, cta0, tid);
    ln_commit(xv, smc + FFN_SA0, tid, sg);
    __syncthreads();

    for (int tt = 0; tt < NT; tt++) {
        const size_t base = cta0 + (size_t)tt * TOKS;
        const unsigned curA = sbase + (((tt & 1) == 0) ? FFN_SA0 : FFN_SA1);
        const unsigned nxtOff = (((tt & 1) == 0) ? FFN_SA1 : FFN_SA0);

        float acc[16][4];
#pragma unroll
        for (int m = 0; m < 16; m++)
#pragma unroll
            for (int p = 0; p < 4; p++) acc[m][p] = 0.f;

#pragma unroll
        for (int ks = 0; ks < 4; ks++) {
            const int k0 = ks * 16;
            unsigned a0,a1,a2,a3;
            {
                int ar = t0 + (lane & 15);
                int ac = (k0 >> 3) + (lane >> 4);
                unsigned aaddr = curA + ar*128 + ((ac ^ (ar & 7)) << 4);
                LDSM4(a0,a1,a2,a3, aaddr);
            }
#pragma unroll
            for (int st = 0; st < 8; st++) {
                int n0 = jbase + st * 16;
                unsigned b0,b1r,b2,b3;
                int br = k0 + (lane & 15);
                int bc = (n0 >> 3) + (lane >> 4);
                unsigned baddr = sbase + FFN_SW1 + br*512 + ((bc ^ (br & 7)) << 4);
                LDSM4T(b0,b1r,b2,b3, baddr);
                MMA16816(acc[2*st][0],acc[2*st][1],acc[2*st][2],acc[2*st][3],
                         a0,a1,a2,a3, b0,b1r);
                MMA16816(acc[2*st+1][0],acc[2*st+1][1],acc[2*st+1][2],acc[2*st+1][3],
                         a0,a1,a2,a3, b2,b3);
            }
        }

        unsigned pk[8][4];
#pragma unroll
        for (int m = 0; m < 16; m++) {
            int col = jbase + m*8 + 2*tig;
            float bb0 = sb1[col], bb1 = sb1[col+1];
            float h00 = gelu_f(acc[m][0] + bb0);
            float h01 = gelu_f(acc[m][1] + bb1);
            float h10 = gelu_f(acc[m][2] + bb0);
            float h11 = gelu_f(acc[m][3] + bb1);
            if ((m & 1) == 0) {
                pk[m>>1][0] = bf2u(h00, h01);
                pk[m>>1][1] = bf2u(h10, h11);
            } else {
                pk[m>>1][2] = bf2u(h00, h01);
                pk[m>>1][3] = bf2u(h10, h11);
            }
        }

        if (tt + 1 < NT) ln_prefetch(xv, xin, base + TOKS, tid);

        float acc2[8][4];
#pragma unroll
        for (int m = 0; m < 8; m++)
#pragma unroll
            for (int p = 0; p < 4; p++) acc2[m][p] = 0.f;

#pragma unroll
        for (int ks = 0; ks < 8; ks++) {
            const int br = jbase + ks*16 + (lane & 15);
#pragma unroll
            for (int st = 0; st < 4; st++) {
                int n0 = st * 16;
                unsigned b0,b1r,b2,b3;
                int bc = (n0 >> 3) + (lane >> 4);
                unsigned baddr = sbase + FFN_SW2 + br*128 + ((bc ^ (br & 7)) << 4);
                LDSM4T(b0,b1r,b2,b3, baddr);
                MMA16816(acc2[2*st][0],acc2[2*st][1],acc2[2*st][2],acc2[2*st][3],
                         pk[ks][0],pk[ks][1],pk[ks][2],pk[ks][3], b0,b1r);
                MMA16816(acc2[2*st+1][0],acc2[2*st+1][1],acc2[2*st+1][2],acc2[2*st+1][3],
                         pk[ks][0],pk[ks][1],pk[ks][2],pk[ks][3], b2,b3);
            }
        }

        float* red = (float*)(smc + FFN_SRED) + tw * (16*68);
        const int st_sto = (nh == 1) ? 0 : 4;
        const int st_fin = (nh == 1) ? 4 : 0;
#pragma unroll
        for (int s = 0; s < 4; s++) {
            int st = st_sto + s;
#pragma unroll
            for (int rp = 0; rp < 2; rp++) {
                int row = gid + rp*8;
                *(float2*)(red + row*68 + st*8 + 2*tig) =
                    make_float2(acc2[st][2*rp], acc2[st][2*rp+1]);
            }
        }
        __syncthreads();
#pragma unroll
        for (int s = 0; s < 4; s++) {
            int st = st_fin + s;
            int e = st*8 + 2*tig;
            float bb0 = sb2[e], bb1 = sb2[e+1];
#pragma unroll
            for (int rp = 0; rp < 2; rp++) {
                int row = gid + rp*8;
                float2 r = *(const float2*)(red + row*68 + e);
                float2 x = *(const float2*)(xin + (base + t0 + row)*64 + e);
                float2 o = make_float2(x.x + r.x + acc2[st][2*rp]   + bb0,
                                       x.y + r.y + acc2[st][2*rp+1] + bb1);
                *(float2*)(xout + (base + t0 + row)*64 + e) = o;
            }
        }

        if (tt + 1 < NT) ln_commit(xv, smc + nxtOff, tid, sg);
        __syncthreads();
    }
}

// ==================================================================
// Attention kernel: out = x + attn(LN(x)) ; NT tiles/CTA
// phase1: warp = 32t x 48c. phases 2+3 FUSED: warp = batch b (wid>>1),
// heads hbase..+3 (hbase=(wid&1)*4); P·V outputs repacked in regs as
// A-frags of the projection GEMM over the warp's 32-col c-slab;
// 2-way balanced-halves reduction with partner wid^1.
// ==================================================================
#define ATT_ST    0
#define ATT_SWP   24576
#define ATT_SA0   32768
#define ATT_SA1   40960
#define ATT_SQKV  49152
#define ATT_SRED  73728           // 8 regions x 16 rows x 34 floats = 17408
#define ATT_SBQKV 91136
#define ATT_SBP   91904
#define ATT_SG    92160
#define ATT_SMEM_BYTES 92672

template <bool CAUSAL>
__global__ void __launch_bounds__(TPB, 2) attn_kernel(
    const float* __restrict__ xin, float* __restrict__ xout,
    const __nv_bfloat16* __restrict__ Tqkv, const __nv_bfloat16* __restrict__ Wpb,
    const float* __restrict__ bq, const float* __restrict__ bk,
    const float* __restrict__ bv, const float* __restrict__ bp,
    const float* __restrict__ g1, const float* __restrict__ be1)
{
    extern __shared__ char smc[];
    float* sbqkv = (float*)(smc + ATT_SBQKV);
    float* sbp   = (float*)(smc + ATT_SBP);
    float* sg    = (float*)(smc + ATT_SG);

    const int tid = threadIdx.x;
    const unsigned sbase = su32(smc);

    {
        const uint4* srcT = (const uint4*)Tqkv;   // 64 rows x 24 chunks
        for (int c = tid; c < 1536; c += TPB) {
            int r = c / 24, ch = c % 24;
            *(uint4*)(smc + ATT_ST + r*384 + ((ch ^ (r & 7)) << 4)) = srcT[c];
        }
        const uint4* srcP = (const uint4*)Wpb;
        for (int c = tid; c < 512; c += TPB) {
            int r = c >> 3, ch = c & 7;
            *(uint4*)(smc + ATT_SWP + r*128 + ((ch ^ (r & 7)) << 4)) = srcP[c];
        }
    }
    if (tid < 192) sbqkv[tid] = (tid < 64) ? bq[tid] : (tid < 128 ? bk[tid-64] : bv[tid-128]);
    if (tid < 64)  sbp[tid] = bp[tid];
    if (tid < 128) sg[tid] = (tid < 64) ? g1[tid] : be1[tid-64];
    __syncthreads();

    const int lane = tid & 31, wid = tid >> 5;
    const int gid = lane >> 2, tig = lane & 3;
    const int tg = wid & 1, cg = wid >> 1;    // phase-1 mapping: 32t x 48c
    const int tb0 = tg * 32;
    // fused phase 2+3 mapping
    const int pb   = wid >> 1;                // batch 0..3
    const int w01  = wid & 1;                 // head-half: c-slab [w01*32, +32)
    const int hbase = w01 * 4;
    float* rsto = (float*)(smc + ATT_SRED) + (pb*2 + (w01^1)) * (16*34);
    float* rfin = (float*)(smc + ATT_SRED) + (pb*2 + w01)     * (16*34);

    const size_t cta0 = (size_t)blockIdx.x * NT * TOKS;

    float xv[16];
    ln_prefetch(xv, xin, cta0, tid);
    ln_commit(xv, smc + ATT_SA0, tid, sg);
    __syncthreads();

    for (int tt = 0; tt < NT; tt++) {
        const size_t base = cta0 + (size_t)tt * TOKS;
        const unsigned curA = sbase + (((tt & 1) == 0) ? ATT_SA0 : ATT_SA1);
        const unsigned nxtOff = (((tt & 1) == 0) ? ATT_SA1 : ATT_SA0);

        // ---------- phase 1: QKV = A @ T + b ; warp = 32t x 48c ----------
        {
            float acc[2][6][4];
#pragma unroll
            for (int mi = 0; mi < 2; mi++)
#pragma unroll
                for (int m = 0; m < 6; m++)
#pragma unroll
                    for (int p = 0; p < 4; p++) acc[mi][m][p] = 0.f;

#pragma unroll
            for (int ks = 0; ks < 4; ks++) {
                const int k0 = ks * 16;
                unsigned aA[2][4];
#pragma unroll
                for (int mi = 0; mi < 2; mi++) {
                    int ar = tb0 + mi*16 + (lane & 15);
                    int ac = (k0 >> 3) + (lane >> 4);
                    unsigned aaddr = curA + ar*128 + ((ac ^ (ar & 7)) << 4);
                    LDSM4(aA[mi][0], aA[mi][1], aA[mi][2], aA[mi][3], aaddr);
                }
#pragma unroll
                for (int st = 0; st < 3; st++) {
                    int n0 = cg*48 + st * 16;
                    unsigned b0,b1r,b2,b3;
                    int br = k0 + (lane & 15);
                    int bc = (n0 >> 3) + (lane >> 4);
                    unsigned baddr = sbase + ATT_ST + br*384 + ((bc ^ (br & 7)) << 4);
                    LDSM4T(b0,b1r,b2,b3, baddr);
#pragma unroll
                    for (int mi = 0; mi < 2; mi++) {
                        MMA16816(acc[mi][2*st][0],acc[mi][2*st][1],acc[mi][2*st][2],acc[mi][2*st][3],
                                 aA[mi][0],aA[mi][1],aA[mi][2],aA[mi][3], b0,b1r);
                        MMA16816(acc[mi][2*st+1][0],acc[mi][2*st+1][1],acc[mi][2*st+1][2],acc[mi][2*st+1][3],
                                 aA[mi][0],aA[mi][1],aA[mi][2],aA[mi][3], b2,b3);
                    }
                }
            }

            if (tt + 1 < NT) ln_prefetch(xv, xin, base + TOKS, tid);

#pragma unroll
            for (int mi = 0; mi < 2; mi++)
#pragma unroll
                for (int nf = 0; nf < 6; nf++) {
                    int cc = cg*48 + nf*8;
                    int sec = cc >> 6;               // 0=q 1=k 2=v
                    int h = (cc >> 3) & 7;
                    int c = cc + 2*tig;
                    int b_loc = tg*2 + mi;
                    float bb0 = sbqkv[c], bb1 = sbqkv[c+1];
                    float scale = (sec == 0) ? 0.35355339059327373f : 1.f;
                    float v00 = (acc[mi][nf][0] + bb0) * scale, v01 = (acc[mi][nf][1] + bb1) * scale;
                    float v10 = (acc[mi][nf][2] + bb0) * scale, v11 = (acc[mi][nf][3] + bb1) * scale;
                    unsigned tb = ATT_SQKV + sec*8192 + (b_loc*8 + h)*256 + tig*4;
                    *(unsigned*)(smc + tb + gid*16)     = bf2u(v00, v01);
                    *(unsigned*)(smc + tb + (gid+8)*16) = bf2u(v10, v11);
                }
        }
        __syncthreads();

        // ---------- fused phases 2+3 ----------
        {
            unsigned pa[2][4];      // projection A-frags (k-chunk = 2 heads)

            // paired-LDSM4 attention core: 2 iterations x 2 head-pairs
#pragma unroll
            for (int ii = 0; ii < 2; ii++) {
                const int h0 = hbase + 2*ii;
                const unsigned taddr = sbase + ATT_SQKV + (pb*8 + h0)*256
                                       + (lane >> 4)*256 + (lane & 15)*16;
                unsigned q0,q1,q2,q3, k0,k1,k2,k3, v0,v1,v2,v3;
                LDSM4 (q0,q1,q2,q3, taddr);           // Q tiles h0, h0+1
                LDSM4 (k0,k1,k2,k3, taddr + 8192);    // K
                LDSM4T(v0,v1,v2,v3, taddr + 16384);   // V

#pragma unroll
                for (int j = 0; j < 2; j++) {
                    unsigned qa0 = j ? q2 : q0, qa1 = j ? q3 : q1;
                    unsigned kb0 = j ? k2 : k0, kb1 = j ? k3 : k1;
                    unsigned vb0 = j ? v2 : v0, vb1 = j ? v3 : v1;

                    float s0=0,s1=0,s2=0,s3=0,s4=0,s5=0,s6=0,s7=0;
                    MMA16808(s0,s1,s2,s3, qa0,qa1, kb0);   // u = 2tig,2tig+1
                    MMA16808(s4,s5,s6,s7, qa0,qa1, kb1);   // u = 2tig+8,2tig+9

                    if (CAUSAL) {
                        const int u0 = 2*tig, u1 = 2*tig+1, u2 = 2*tig+8, u3 = 2*tig+9;
                        if (u0 > gid)   s0 = -1e30f;
                        if (u1 > gid)   s1 = -1e30f;
                        if (u2 > gid)   s4 = -1e30f;
                        if (u3 > gid)   s5 = -1e30f;
                        if (u0 > gid+8) s2 = -1e30f;
                        if (u1 > gid+8) s3 = -1e30f;
                        if (u2 > gid+8) s6 = -1e30f;
                        if (u3 > gid+8) s7 = -1e30f;
                    }
                    float e0 = __expf(s0), e1 = __expf(s1);
                    float e4 = __expf(s4), e5 = __expf(s5);
                    float e2 = __expf(s2), e3 = __expf(s3);
                    float e6 = __expf(s6), e7 = __expf(s7);
                    float slo = e0+e1+e4+e5, shi = e2+e3+e6+e7;
                    slo += __shfl_xor_sync(0xffffffffu, slo, 1);
                    slo += __shfl_xor_sync(0xffffffffu, slo, 2);
                    shi += __shfl_xor_sync(0xffffffffu, shi, 1);
                    shi += __shfl_xor_sync(0xffffffffu, shi, 2);
                    const float ilo = 1.f/slo, ihi = 1.f/shi;

                    unsigned p0 = bf2u(e0, e1);
                    unsigned p1 = bf2u(e2, e3);
                    unsigned p2 = bf2u(e4, e5);
                    unsigned p3 = bf2u(e6, e7);

                    float o0=0,o1=0,o2=0,o3=0;
                    MMA16816(o0,o1,o2,o3, p0,p1,p2,p3, vb0,vb1);
                    o0 *= ilo; o1 *= ilo; o2 *= ihi; o3 *= ihi;

                    // pack directly as A-frag of projection (chunk ii, head j)
                    pa[ii][2*j]     = bf2u(o0, o1);   // row gid
                    pa[ii][2*j + 1] = bf2u(o2, o3);   // row gid+8
                }
            }

            // projection partial: out16x64 over c-slab [w01*32, +32)
            float acc3[8][4];
#pragma unroll
            for (int m = 0; m < 8; m++)
#pragma unroll
                for (int p = 0; p < 4; p++) acc3[m][p] = 0.f;

#pragma unroll
            for (int kc = 0; kc < 2; kc++) {
                const int c0 = (hbase + 2*kc) * 8;
                const int br = c0 + (lane & 15);
#pragma unroll
                for (int st = 0; st < 4; st++) {
                    unsigned b0,b1r,b2,b3;
                    int bc = st*2 + (lane >> 4);
                    unsigned baddr = sbase + ATT_SWP + br*128 + ((bc ^ (br & 7)) << 4);
                    LDSM4T(b0,b1r,b2,b3, baddr);
                    MMA16816(acc3[2*st][0],acc3[2*st][1],acc3[2*st][2],acc3[2*st][3],
                             pa[kc][0],pa[kc][1],pa[kc][2],pa[kc][3], b0,b1r);
                    MMA16816(acc3[2*st+1][0],acc3[2*st+1][1],acc3[2*st+1][2],acc3[2*st+1][3],
                             pa[kc][0],pa[kc][1],pa[kc][2],pa[kc][3], b2,b3);
                }
            }

            // 2-way balanced-halves reduction with partner wid^1
            // w01==0: store nf 4..7 (cols 32-63), finalize nf 0..3; w01==1: reverse.
            const int nf_sto = (w01 == 0) ? 4 : 0;
            const int nf_fin = 4 - nf_sto;
#pragma unroll
            for (int s = 0; s < 4; s++) {
                int nf = nf_sto + s;
                int col = (nf & 3)*8 + 2*tig;
#pragma unroll
                for (int rp = 0; rp < 2; rp++) {
                    int row = gid + rp*8;
                    *(float2*)(rsto + row*34 + col) =
                        make_float2(acc3[nf][2*rp], acc3[nf][2*rp+1]);
                }
            }
            __syncthreads();
#pragma unroll
            for (int s = 0; s < 4; s++) {
                int nf = nf_fin + s;
                int e = nf*8 + 2*tig;
                int col = (nf & 3)*8 + 2*tig;
                float bb0 = sbp[e], bb1 = sbp[e+1];
#pragma unroll
                for (int rp = 0; rp < 2; rp++) {
                    int row = gid + rp*8;
                    float2 v = *(const float2*)(rfin + row*34 + col);
                    size_t tok = base + pb*16 + row;
                    float2 x = *(const float2*)(xin + tok*64 + e);
                    float2 o = make_float2(x.x + v.x + acc3[nf][2*rp]   + bb0,
                                           x.y + v.y + acc3[nf][2*rp+1] + bb1);
                    *(float2*)(xout + tok*64 + e) = o;
                }
            }
        }

        if (tt + 1 < NT) ln_commit(xv, smc + nxtOff, tid, sg);
        __syncthreads();
    }
}

// ==================================================================
// launch: prep -> attn(u) -> ffn -> attn(m, causal) -> ffn
// ==================================================================
extern "C" void kernel_launch(void* const* d_in, const int* in_sizes, int n_in,
                              void* d_out, int out_size)
{
    (void)in_sizes; (void)n_in; (void)out_size;
    const float* x   = (const float*)d_in[0];
    const float* uWq = (const float*)d_in[1];  const float* ubq = (const float*)d_in[2];
    const float* uWk = (const float*)d_in[3];  const float* ubk = (const float*)d_in[4];
    const float* uWv = (const float*)d_in[5];  const float* ubv = (const float*)d_in[6];
    const float* uWp = (const float*)d_in[7];  const float* ubp = (const float*)d_in[8];
    const float* mWq = (const float*)d_in[9];  const float* mbq = (const float*)d_in[10];
    const float* mWk = (const float*)d_in[11]; const float* mbk = (const float*)d_in[12];
    const float* mWv = (const float*)d_in[13]; const float* mbv = (const float*)d_in[14];
    const float* mWp = (const float*)d_in[15]; const float* mbp = (const float*)d_in[16];
    const float* fW1 = (const float*)d_in[17]; const float* fb1 = (const float*)d_in[18];
    const float* fW2 = (const float*)d_in[19]; const float* fb2 = (const float*)d_in[20];
    const float* g1  = (const float*)d_in[21]; const float* be1 = (const float*)d_in[22];
    const float* g2  = (const float*)d_in[23]; const float* be2 = (const float*)d_in[24];
    float* out = (float*)d_out;

    float* scratch = nullptr;
    cudaGetSymbolAddress((void**)&scratch, g_scratch);
    __nv_bfloat16 *Tu = nullptr, *Tm = nullptr, *Wpu = nullptr, *Wpm = nullptr;
    cudaGetSymbolAddress((void**)&Tu, g_Tu);
    cudaGetSymbolAddress((void**)&Tm, g_Tm);
    cudaGetSymbolAddress((void**)&Wpu, g_Wpu);
    cudaGetSymbolAddress((void**)&Wpm, g_Wpm);

    cudaFuncSetAttribute(attn_kernel<false>, cudaFuncAttributeMaxDynamicSharedMemorySize, ATT_SMEM_BYTES);
    cudaFuncSetAttribute(attn_kernel<true>,  cudaFuncAttributeMaxDynamicSharedMemorySize, ATT_SMEM_BYTES);
    cudaFuncSetAttribute(ffn_kernel,         cudaFuncAttributeMaxDynamicSharedMemorySize, FFN_SMEM_BYTES);

    prep_kernel<<<64, 256>>>(fW1, fW2, uWq, uWk, uWv, uWp, mWq, mWk, mWv, mWp);

    attn_kernel<false><<<NBLK, TPB, ATT_SMEM_BYTES>>>(x, scratch, Tu, Wpu,
        ubq, ubk, ubv, ubp, g1, be1);
    ffn_kernel<<<NBLK, TPB, FFN_SMEM_BYTES>>>(scratch, out, fb1, fb2, g2, be2);
    attn_kernel<true><<<NBLK, TPB, ATT_SMEM_BYTES>>>(out, scratch, Tm, Wpm,
        mbq, mbk, mbv, mbp, g1, be1);
    ffn_kernel<<<NBLK, TPB, FFN_SMEM_BYTES>>>(scratch, out, fb1, fb2, g2, be2);
}

// round 13
// speedup vs baseline: 1.2175x; 1.1250x over previous
#include <cuda_runtime.h>
#include <cuda_bf16.h>
#include <math.h>

#define NTOK (32768*16)          // 524288 tokens
#define TPB  256
#define TOKS 64                  // tokens per tile
#define NT   4                   // tiles per CTA
#define NBLK (NTOK/(TOKS*NT))    // 2048 CTAs

// ---------------- device globals (allocation-free scratch) ----------------
__device__ float g_scratch[(size_t)NTOK * 64];
__device__ __align__(16) __nv_bfloat16 g_W1b[64*256];
__device__ __align__(16) __nv_bfloat16 g_W2b[256*64];
__device__ __align__(16) __nv_bfloat16 g_Tu[64*192];   // [d][h*8+s (+0/64/128 for q/k/v)]
__device__ __align__(16) __nv_bfloat16 g_Tm[64*192];
__device__ __align__(16) __nv_bfloat16 g_Wpu[64*64];
__device__ __align__(16) __nv_bfloat16 g_Wpm[64*64];

// ---------------- small helpers ----------------
__device__ __forceinline__ unsigned bf2u(float a, float b) {
    unsigned r;
    asm("cvt.rn.bf16x2.f32 %0, %1, %2;" : "=r"(r) : "f"(b), "f"(a));
    return r;
}
__device__ __forceinline__ unsigned su32(const void* p) {
    return (unsigned)__cvta_generic_to_shared(p);
}
// fast GELU: 0.5z(1+tanh(0.79788456(z + 0.044715 z^3))), HW tanh
__device__ __forceinline__ float gelu_f(float z) {
    float w = z * fmaf(0.035677408136f, z*z, 0.79788456080287f);
    float t;
    asm("tanh.approx.f32 %0, %1;" : "=f"(t) : "f"(w));
    float hz = 0.5f*z;
    return fmaf(hz, t, hz);
}

#define LDSM4(r0,r1,r2,r3,addr) \
    asm volatile("ldmatrix.sync.aligned.m8n8.x4.shared.b16 {%0,%1,%2,%3},[%4];" \
        : "=r"(r0),"=r"(r1),"=r"(r2),"=r"(r3) : "r"(addr))
#define LDSM4T(r0,r1,r2,r3,addr) \
    asm volatile("ldmatrix.sync.aligned.m8n8.x4.trans.shared.b16 {%0,%1,%2,%3},[%4];" \
        : "=r"(r0),"=r"(r1),"=r"(r2),"=r"(r3) : "r"(addr))
#define MMA16816(c0,c1,c2,c3,a0,a1,a2,a3,b0,b1) \
    asm volatile("mma.sync.aligned.m16n8k16.row.col.f32.bf16.bf16.f32 " \
        "{%0,%1,%2,%3},{%4,%5,%6,%7},{%8,%9},{%0,%1,%2,%3};" \
        : "+f"(c0),"+f"(c1),"+f"(c2),"+f"(c3) \
        : "r"(a0),"r"(a1),"r"(a2),"r"(a3),"r"(b0),"r"(b1))
#define MMA16808(c0,c1,c2,c3,a0,a1,b0) \
    asm volatile("mma.sync.aligned.m16n8k8.row.col.f32.bf16.bf16.f32 " \
        "{%0,%1,%2,%3},{%4,%5},{%6},{%0,%1,%2,%3};" \
        : "+f"(c0),"+f"(c1),"+f"(c2),"+f"(c3) \
        : "r"(a0),"r"(a1),"r"(b0))

// ---- LN split into prefetch (LDG only) + commit (shuffle + STS) ----
__device__ __forceinline__ void ln_prefetch(float* xv, const float* __restrict__ xin,
                                            size_t base, int tid) {
    const int t = tid >> 2, qp = tid & 3;
    const float4* x4 = (const float4*)(xin + (base + t)*64) + qp*4;
#pragma unroll
    for (int i = 0; i < 4; i++) {
        float4 v = x4[i];
        xv[4*i]=v.x; xv[4*i+1]=v.y; xv[4*i+2]=v.z; xv[4*i+3]=v.w;
    }
}
__device__ __forceinline__ void ln_commit(const float* xv, char* __restrict__ sA,
                                          int tid, const float* __restrict__ sg) {
    const int t = tid >> 2, qp = tid & 3;
    float s = 0.f, ss = 0.f;
#pragma unroll
    for (int i = 0; i < 16; i++) { s += xv[i]; ss = fmaf(xv[i], xv[i], ss); }
    s  += __shfl_xor_sync(0xffffffffu, s, 1);  ss += __shfl_xor_sync(0xffffffffu, ss, 1);
    s  += __shfl_xor_sync(0xffffffffu, s, 2);  ss += __shfl_xor_sync(0xffffffffu, ss, 2);
    const float mean = s * (1.f/64.f);
    const float var  = ss * (1.f/64.f) - mean*mean;
    const float rstd = rsqrtf(var + 1e-5f);
    const int kb = qp * 16;
#pragma unroll
    for (int c = 0; c < 2; c++) {
        float v[8];
#pragma unroll
        for (int e = 0; e < 8; e++) {
            int k = kb + c*8 + e;
            v[e] = (xv[c*8+e] - mean) * rstd * sg[k] + sg[64+k];
        }
        uint4 q;
        q.x = bf2u(v[0], v[1]); q.y = bf2u(v[2], v[3]);
        q.z = bf2u(v[4], v[5]); q.w = bf2u(v[6], v[7]);
        int ch = qp*2 + c;
        *(uint4*)(sA + t*128 + ((ch ^ (t & 7)) << 4)) = q;
    }
}

// ---------------- prep: fp32 weights -> bf16 (and qkv transpose) ----------------
__global__ void prep_kernel(const float* __restrict__ W1, const float* __restrict__ W2,
                            const float* __restrict__ uWq, const float* __restrict__ uWk,
                            const float* __restrict__ uWv, const float* __restrict__ uWp,
                            const float* __restrict__ mWq, const float* __restrict__ mWk,
                            const float* __restrict__ mWv, const float* __restrict__ mWp)
{
    int i0 = blockIdx.x * blockDim.x + threadIdx.x;
    int stride = gridDim.x * blockDim.x;
    for (int i = i0; i < 16384; i += stride) {
        g_W1b[i] = __float2bfloat16(W1[i]);
        g_W2b[i] = __float2bfloat16(W2[i]);
    }
    for (int i = i0; i < 4096; i += stride) {
        int h = i >> 9, d = (i >> 3) & 63, s = i & 7;
        int c = h*8 + s;
        g_Tu[d*192 + c]       = __float2bfloat16(uWq[i]);
        g_Tu[d*192 + 64 + c]  = __float2bfloat16(uWk[i]);
        g_Tu[d*192 + 128 + c] = __float2bfloat16(uWv[i]);
        g_Tm[d*192 + c]       = __float2bfloat16(mWq[i]);
        g_Tm[d*192 + 64 + c]  = __float2bfloat16(mWk[i]);
        g_Tm[d*192 + 128 + c] = __float2bfloat16(mWv[i]);
        g_Wpu[i] = __float2bfloat16(uWp[i]);
        g_Wpm[i] = __float2bfloat16(mWp[i]);
    }
}

// ==================================================================
// FFN kernel (R8 proven design): out = x + gelu(LN(x)@W1 + b1)@W2 + b2
// ==================================================================
#define FFN_SW1  0
#define FFN_SW2  32768
#define FFN_SA0  65536
#define FFN_SA1  73728
#define FFN_SRED 81920            // 4 groups x 16 x 68 floats = 17408
#define FFN_SB1  99328
#define FFN_SB2  100352
#define FFN_SG   100608
#define FFN_SMEM_BYTES 101120

__global__ void __launch_bounds__(TPB, 2) ffn_kernel(
    const float* __restrict__ xin, float* __restrict__ xout,
    const float* __restrict__ b1, const float* __restrict__ b2,
    const float* __restrict__ g2, const float* __restrict__ be2)
{
    extern __shared__ char smc[];
    float* sb1 = (float*)(smc + FFN_SB1);
    float* sb2 = (float*)(smc + FFN_SB2);
    float* sg  = (float*)(smc + FFN_SG);

    const int tid = threadIdx.x;
    const unsigned sbase = su32(smc);

    {
        const uint4* src1 = (const uint4*)g_W1b;
        const uint4* src2 = (const uint4*)g_W2b;
        for (int c = tid; c < 2048; c += TPB) {
            int r1 = c >> 5, c1 = c & 31;
            *(uint4*)(smc + FFN_SW1 + r1*512 + ((c1 ^ (r1 & 7)) << 4)) = src1[c];
            int r2 = c >> 3, c2 = c & 7;
            *(uint4*)(smc + FFN_SW2 + r2*128 + ((c2 ^ (r2 & 7)) << 4)) = src2[c];
        }
    }
    sb1[tid] = b1[tid];
    if (tid < 64) { sb2[tid] = b2[tid]; sg[tid] = g2[tid]; sg[64+tid] = be2[tid]; }
    __syncthreads();

    const int lane = tid & 31, wid = tid >> 5;
    const int gid = lane >> 2, tig = lane & 3;
    const int tw = wid & 3, nh = wid >> 2;
    const int t0 = tw * 16;
    const int jbase = nh * 128;

    const size_t cta0 = (size_t)blockIdx.x * NT * TOKS;

    float xv[16];
    ln_prefetch(xv, xin, cta0, tid);
    ln_commit(xv, smc + FFN_SA0, tid, sg);
    __syncthreads();

    for (int tt = 0; tt < NT; tt++) {
        const size_t base = cta0 + (size_t)tt * TOKS;
        const unsigned curA = sbase + (((tt & 1) == 0) ? FFN_SA0 : FFN_SA1);
        const unsigned nxtOff = (((tt & 1) == 0) ? FFN_SA1 : FFN_SA0);

        float acc[16][4];
#pragma unroll
        for (int m = 0; m < 16; m++)
#pragma unroll
            for (int p = 0; p < 4; p++) acc[m][p] = 0.f;

#pragma unroll
        for (int ks = 0; ks < 4; ks++) {
            const int k0 = ks * 16;
            unsigned a0,a1,a2,a3;
            {
                int ar = t0 + (lane & 15);
                int ac = (k0 >> 3) + (lane >> 4);
                unsigned aaddr = curA + ar*128 + ((ac ^ (ar & 7)) << 4);
                LDSM4(a0,a1,a2,a3, aaddr);
            }
#pragma unroll
            for (int st = 0; st < 8; st++) {
                int n0 = jbase + st * 16;
                unsigned b0,b1r,b2,b3;
                int br = k0 + (lane & 15);
                int bc = (n0 >> 3) + (lane >> 4);
                unsigned baddr = sbase + FFN_SW1 + br*512 + ((bc ^ (br & 7)) << 4);
                LDSM4T(b0,b1r,b2,b3, baddr);
                MMA16816(acc[2*st][0],acc[2*st][1],acc[2*st][2],acc[2*st][3],
                         a0,a1,a2,a3, b0,b1r);
                MMA16816(acc[2*st+1][0],acc[2*st+1][1],acc[2*st+1][2],acc[2*st+1][3],
                         a0,a1,a2,a3, b2,b3);
            }
        }

        unsigned pk[8][4];
#pragma unroll
        for (int m = 0; m < 16; m++) {
            int col = jbase + m*8 + 2*tig;
            float bb0 = sb1[col], bb1 = sb1[col+1];
            float h00 = gelu_f(acc[m][0] + bb0);
            float h01 = gelu_f(acc[m][1] + bb1);
            float h10 = gelu_f(acc[m][2] + bb0);
            float h11 = gelu_f(acc[m][3] + bb1);
            if ((m & 1) == 0) {
                pk[m>>1][0] = bf2u(h00, h01);
                pk[m>>1][1] = bf2u(h10, h11);
            } else {
                pk[m>>1][2] = bf2u(h00, h01);
                pk[m>>1][3] = bf2u(h10, h11);
            }
        }

        if (tt + 1 < NT) ln_prefetch(xv, xin, base + TOKS, tid);

        float acc2[8][4];
#pragma unroll
        for (int m = 0; m < 8; m++)
#pragma unroll
            for (int p = 0; p < 4; p++) acc2[m][p] = 0.f;

#pragma unroll
        for (int ks = 0; ks < 8; ks++) {
            const int br = jbase + ks*16 + (lane & 15);
#pragma unroll
            for (int st = 0; st < 4; st++) {
                int n0 = st * 16;
                unsigned b0,b1r,b2,b3;
                int bc = (n0 >> 3) + (lane >> 4);
                unsigned baddr = sbase + FFN_SW2 + br*128 + ((bc ^ (br & 7)) << 4);
                LDSM4T(b0,b1r,b2,b3, baddr);
                MMA16816(acc2[2*st][0],acc2[2*st][1],acc2[2*st][2],acc2[2*st][3],
                         pk[ks][0],pk[ks][1],pk[ks][2],pk[ks][3], b0,b1r);
                MMA16816(acc2[2*st+1][0],acc2[2*st+1][1],acc2[2*st+1][2],acc2[2*st+1][3],
                         pk[ks][0],pk[ks][1],pk[ks][2],pk[ks][3], b2,b3);
            }
        }

        float* red = (float*)(smc + FFN_SRED) + tw * (16*68);
        const int st_sto = (nh == 1) ? 0 : 4;
        const int st_fin = (nh == 1) ? 4 : 0;
#pragma unroll
        for (int s = 0; s < 4; s++) {
            int st = st_sto + s;
#pragma unroll
            for (int rp = 0; rp < 2; rp++) {
                int row = gid + rp*8;
                *(float2*)(red + row*68 + st*8 + 2*tig) =
                    make_float2(acc2[st][2*rp], acc2[st][2*rp+1]);
            }
        }
        __syncthreads();
#pragma unroll
        for (int s = 0; s < 4; s++) {
            int st = st_fin + s;
            int e = st*8 + 2*tig;
            float bb0 = sb2[e], bb1 = sb2[e+1];
#pragma unroll
            for (int rp = 0; rp < 2; rp++) {
                int row = gid + rp*8;
                float2 r = *(const float2*)(red + row*68 + e);
                float2 x = *(const float2*)(xin + (base + t0 + row)*64 + e);
                float2 o = make_float2(x.x + r.x + acc2[st][2*rp]   + bb0,
                                       x.y + r.y + acc2[st][2*rp+1] + bb1);
                *(float2*)(xout + (base + t0 + row)*64 + e) = o;
            }
        }

        if (tt + 1 < NT) ln_commit(xv, smc + nxtOff, tid, sg);
        __syncthreads();
    }
}

// ==================================================================
// Attention kernel (R10 design + paired-LDSM4 core): out = x + attn(LN(x))
// phase1: warp = 32t x 48c; phase2: paired ldmatrix.x4, sOb writeback;
// phase3: warp = 16t x 32e.
// ==================================================================
#define ATT_ST    0
#define ATT_SWP   24576
#define ATT_SA0   32768
#define ATT_SA1   40960
#define ATT_SOB   49152
#define ATT_SQKV  57344
#define ATT_SBQKV 81920
#define ATT_SBP   82688
#define ATT_SG    82944
#define ATT_SMEM_BYTES 83456

template <bool CAUSAL>
__global__ void __launch_bounds__(TPB, 2) attn_kernel(
    const float* __restrict__ xin, float* __restrict__ xout,
    const __nv_bfloat16* __restrict__ Tqkv, const __nv_bfloat16* __restrict__ Wpb,
    const float* __restrict__ bq, const float* __restrict__ bk,
    const float* __restrict__ bv, const float* __restrict__ bp,
    const float* __restrict__ g1, const float* __restrict__ be1)
{
    extern __shared__ char smc[];
    float* sbqkv = (float*)(smc + ATT_SBQKV);
    float* sbp   = (float*)(smc + ATT_SBP);
    float* sg    = (float*)(smc + ATT_SG);

    const int tid = threadIdx.x;
    const unsigned sbase = su32(smc);

    {
        const uint4* srcT = (const uint4*)Tqkv;   // 64 rows x 24 chunks
        for (int c = tid; c < 1536; c += TPB) {
            int r = c / 24, ch = c % 24;
            *(uint4*)(smc + ATT_ST + r*384 + ((ch ^ (r & 7)) << 4)) = srcT[c];
        }
        const uint4* srcP = (const uint4*)Wpb;
        for (int c = tid; c < 512; c += TPB) {
            int r = c >> 3, ch = c & 7;
            *(uint4*)(smc + ATT_SWP + r*128 + ((ch ^ (r & 7)) << 4)) = srcP[c];
        }
    }
    if (tid < 192) sbqkv[tid] = (tid < 64) ? bq[tid] : (tid < 128 ? bk[tid-64] : bv[tid-128]);
    if (tid < 64)  sbp[tid] = bp[tid];
    if (tid < 128) sg[tid] = (tid < 64) ? g1[tid] : be1[tid-64];
    __syncthreads();

    const int lane = tid & 31, wid = tid >> 5;
    const int gid = lane >> 2, tig = lane & 3;
    const int tw = wid & 3, nh = wid >> 2;    // phase-3 mapping
    const int t0 = tw * 16;
    const int tg = wid & 1, cg = wid >> 1;    // phase-1 mapping: 32t x 48c
    const int tb0 = tg * 32;
    // phase-2 mapping: warp owns batch pb, 4 consecutive heads hb..hb+3
    const int pb = wid >> 1;                  // (wid*4)>>3
    const int hb = (wid & 1) * 4;

    const size_t cta0 = (size_t)blockIdx.x * NT * TOKS;

    float xv[16];
    ln_prefetch(xv, xin, cta0, tid);
    ln_commit(xv, smc + ATT_SA0, tid, sg);
    __syncthreads();

    for (int tt = 0; tt < NT; tt++) {
        const size_t base = cta0 + (size_t)tt * TOKS;
        const unsigned curA = sbase + (((tt & 1) == 0) ? ATT_SA0 : ATT_SA1);
        const unsigned nxtOff = (((tt & 1) == 0) ? ATT_SA1 : ATT_SA0);

        // ---------- phase 1: QKV = A @ T + b ; warp = 32t x 48c ----------
        {
            float acc[2][6][4];
#pragma unroll
            for (int mi = 0; mi < 2; mi++)
#pragma unroll
                for (int m = 0; m < 6; m++)
#pragma unroll
                    for (int p = 0; p < 4; p++) acc[mi][m][p] = 0.f;

#pragma unroll
            for (int ks = 0; ks < 4; ks++) {
                const int k0 = ks * 16;
                unsigned aA[2][4];
#pragma unroll
                for (int mi = 0; mi < 2; mi++) {
                    int ar = tb0 + mi*16 + (lane & 15);
                    int ac = (k0 >> 3) + (lane >> 4);
                    unsigned aaddr = curA + ar*128 + ((ac ^ (ar & 7)) << 4);
                    LDSM4(aA[mi][0], aA[mi][1], aA[mi][2], aA[mi][3], aaddr);
                }
#pragma unroll
                for (int st = 0; st < 3; st++) {
                    int n0 = cg*48 + st * 16;
                    unsigned b0,b1r,b2,b3;
                    int br = k0 + (lane & 15);
                    int bc = (n0 >> 3) + (lane >> 4);
                    unsigned baddr = sbase + ATT_ST + br*384 + ((bc ^ (br & 7)) << 4);
                    LDSM4T(b0,b1r,b2,b3, baddr);
#pragma unroll
                    for (int mi = 0; mi < 2; mi++) {
                        MMA16816(acc[mi][2*st][0],acc[mi][2*st][1],acc[mi][2*st][2],acc[mi][2*st][3],
                                 aA[mi][0],aA[mi][1],aA[mi][2],aA[mi][3], b0,b1r);
                        MMA16816(acc[mi][2*st+1][0],acc[mi][2*st+1][1],acc[mi][2*st+1][2],acc[mi][2*st+1][3],
                                 aA[mi][0],aA[mi][1],aA[mi][2],aA[mi][3], b2,b3);
                    }
                }
            }

            if (tt + 1 < NT) ln_prefetch(xv, xin, base + TOKS, tid);

#pragma unroll
            for (int mi = 0; mi < 2; mi++)
#pragma unroll
                for (int nf = 0; nf < 6; nf++) {
                    int cc = cg*48 + nf*8;
                    int sec = cc >> 6;               // 0=q 1=k 2=v
                    int h = (cc >> 3) & 7;
                    int c = cc + 2*tig;
                    int b_loc = tg*2 + mi;
                    float bb0 = sbqkv[c], bb1 = sbqkv[c+1];
                    float scale = (sec == 0) ? 0.35355339059327373f : 1.f;
                    float v00 = (acc[mi][nf][0] + bb0) * scale, v01 = (acc[mi][nf][1] + bb1) * scale;
                    float v10 = (acc[mi][nf][2] + bb0) * scale, v11 = (acc[mi][nf][3] + bb1) * scale;
                    unsigned tb = ATT_SQKV + sec*8192 + (b_loc*8 + h)*256 + tig*4;
                    *(unsigned*)(smc + tb + gid*16)     = bf2u(v00, v01);
                    *(unsigned*)(smc + tb + (gid+8)*16) = bf2u(v10, v11);
                }
        }
        __syncthreads();

        // ---------- phase 2: MMA attention core (paired ldmatrix.x4) ----------
        {
#pragma unroll
            for (int ii = 0; ii < 2; ii++) {
                const int h0 = hb + 2*ii;
                const unsigned taddr = sbase + ATT_SQKV + (pb*8 + h0)*256
                                       + (lane >> 4)*256 + (lane & 15)*16;
                unsigned q0,q1,q2,q3, k0,k1,k2,k3, v0,v1,v2,v3;
                LDSM4 (q0,q1,q2,q3, taddr);           // Q tiles h0, h0+1
                LDSM4 (k0,k1,k2,k3, taddr + 8192);    // K
                LDSM4T(v0,v1,v2,v3, taddr + 16384);   // V

#pragma unroll
                for (int j = 0; j < 2; j++) {
                    const int h = h0 + j;
                    unsigned qa0 = j ? q2 : q0, qa1 = j ? q3 : q1;
                    unsigned kb0 = j ? k2 : k0, kb1 = j ? k3 : k1;
                    unsigned vb0 = j ? v2 : v0, vb1 = j ? v3 : v1;

                    float s0=0,s1=0,s2=0,s3=0,s4=0,s5=0,s6=0,s7=0;
                    MMA16808(s0,s1,s2,s3, qa0,qa1, kb0);   // u = 2tig,2tig+1
                    MMA16808(s4,s5,s6,s7, qa0,qa1, kb1);   // u = 2tig+8,2tig+9

                    if (CAUSAL) {
                        const int u0 = 2*tig, u1 = 2*tig+1, u2 = 2*tig+8, u3 = 2*tig+9;
                        if (u0 > gid)   s0 = -1e30f;
                        if (u1 > gid)   s1 = -1e30f;
                        if (u2 > gid)   s4 = -1e30f;
                        if (u3 > gid)   s5 = -1e30f;
                        if (u0 > gid+8) s2 = -1e30f;
                        if (u1 > gid+8) s3 = -1e30f;
                        if (u2 > gid+8) s6 = -1e30f;
                        if (u3 > gid+8) s7 = -1e30f;
                    }
                    float e0 = __expf(s0), e1 = __expf(s1);
                    float e4 = __expf(s4), e5 = __expf(s5);
                    float e2 = __expf(s2), e3 = __expf(s3);
                    float e6 = __expf(s6), e7 = __expf(s7);
                    float slo = e0+e1+e4+e5, shi = e2+e3+e6+e7;
                    slo += __shfl_xor_sync(0xffffffffu, slo, 1);
                    slo += __shfl_xor_sync(0xffffffffu, slo, 2);
                    shi += __shfl_xor_sync(0xffffffffu, shi, 1);
                    shi += __shfl_xor_sync(0xffffffffu, shi, 2);
                    const float ilo = 1.f/slo, ihi = 1.f/shi;

                    unsigned p0 = bf2u(e0, e1);
                    unsigned p1 = bf2u(e2, e3);
                    unsigned p2 = bf2u(e4, e5);
                    unsigned p3 = bf2u(e6, e7);

                    float o0=0,o1=0,o2=0,o3=0;
                    MMA16816(o0,o1,o2,o3, p0,p1,p2,p3, vb0,vb1);
                    o0 *= ilo; o1 *= ilo; o2 *= ihi; o3 *= ihi;

                    const int tA = pb*16 + gid, tB = tA + 8;
                    const int c = h*8 + 2*tig;
                    unsigned offA = ATT_SOB + tA*128 + (((c>>3) ^ (tA & 7)) << 4) + ((c & 7) << 1);
                    unsigned offB = ATT_SOB + tB*128 + (((c>>3) ^ (tB & 7)) << 4) + ((c & 7) << 1);
                    *(unsigned*)(smc + offA) = bf2u(o0, o1);
                    *(unsigned*)(smc + offB) = bf2u(o2, o3);
                }
            }
        }
        __syncthreads();

        // ---------- phase 3: out = x + O @ Wp + bp ; warp = 16t x 32e ----------
        {
            const int ebase = nh * 32;
            float acc[4][4];
#pragma unroll
            for (int m = 0; m < 4; m++)
#pragma unroll
                for (int p = 0; p < 4; p++) acc[m][p] = 0.f;

#pragma unroll
            for (int ks = 0; ks < 4; ks++) {
                const int k0 = ks * 16;
                unsigned a0,a1,a2,a3;
                {
                    int ar = t0 + (lane & 15);
                    int ac = (k0 >> 3) + (lane >> 4);
                    unsigned aaddr = sbase + ATT_SOB + ar*128 + ((ac ^ (ar & 7)) << 4);
                    LDSM4(a0,a1,a2,a3, aaddr);
                }
#pragma unroll
                for (int st = 0; st < 2; st++) {
                    int n0 = ebase + st * 16;
                    unsigned b0,b1r,b2,b3;
                    int br = k0 + (lane & 15);
                    int bc = (n0 >> 3) + (lane >> 4);
                    unsigned baddr = sbase + ATT_SWP + br*128 + ((bc ^ (br & 7)) << 4);
                    LDSM4T(b0,b1r,b2,b3, baddr);
                    MMA16816(acc[2*st][0],acc[2*st][1],acc[2*st][2],acc[2*st][3],
                             a0,a1,a2,a3, b0,b1r);
                    MMA16816(acc[2*st+1][0],acc[2*st+1][1],acc[2*st+1][2],acc[2*st+1][3],
                             a0,a1,a2,a3, b2,b3);
                }
            }
            const int r0 = t0 + gid, r1 = t0 + gid + 8;
#pragma unroll
            for (int m = 0; m < 4; m++) {
                int e = ebase + m*8 + 2*tig;
                float bb0 = sbp[e], bb1 = sbp[e+1];
                float2 x0 = *(const float2*)(xin + (base + r0)*64 + e);
                float2 x1 = *(const float2*)(xin + (base + r1)*64 + e);
                float2 o0 = make_float2(x0.x + acc[m][0] + bb0, x0.y + acc[m][1] + bb1);
                float2 o1 = make_float2(x1.x + acc[m][2] + bb0, x1.y + acc[m][3] + bb1);
                *(float2*)(xout + (base + r0)*64 + e) = o0;
                *(float2*)(xout + (base + r1)*64 + e) = o1;
            }
        }

        if (tt + 1 < NT) ln_commit(xv, smc + nxtOff, tid, sg);
        __syncthreads();
    }
}

// ==================================================================
// launch: prep -> attn(u) -> ffn -> attn(m, causal) -> ffn
// ==================================================================
extern "C" void kernel_launch(void* const* d_in, const int* in_sizes, int n_in,
                              void* d_out, int out_size)
{
    (void)in_sizes; (void)n_in; (void)out_size;
    const float* x   = (const float*)d_in[0];
    const float* uWq = (const float*)d_in[1];  const float* ubq = (const float*)d_in[2];
    const float* uWk = (const float*)d_in[3];  const float* ubk = (const float*)d_in[4];
    const float* uWv = (const float*)d_in[5];  const float* ubv = (const float*)d_in[6];
    const float* uWp = (const float*)d_in[7];  const float* ubp = (const float*)d_in[8];
    const float* mWq = (const float*)d_in[9];  const float* mbq = (const float*)d_in[10];
    const float* mWk = (const float*)d_in[11]; const float* mbk = (const float*)d_in[12];
    const float* mWv = (const float*)d_in[13]; const float* mbv = (const float*)d_in[14];
    const float* mWp = (const float*)d_in[15]; const float* mbp = (const float*)d_in[16];
    const float* fW1 = (const float*)d_in[17]; const float* fb1 = (const float*)d_in[18];
    const float* fW2 = (const float*)d_in[19]; const float* fb2 = (const float*)d_in[20];
    const float* g1  = (const float*)d_in[21]; const float* be1 = (const float*)d_in[22];
    const float* g2  = (const float*)d_in[23]; const float* be2 = (const float*)d_in[24];
    float* out = (float*)d_out;

    float* scratch = nullptr;
    cudaGetSymbolAddress((void**)&scratch, g_scratch);
    __nv_bfloat16 *Tu = nullptr, *Tm = nullptr, *Wpu = nullptr, *Wpm = nullptr;
    cudaGetSymbolAddress((void**)&Tu, g_Tu);
    cudaGetSymbolAddress((void**)&Tm, g_Tm);
    cudaGetSymbolAddress((void**)&Wpu, g_Wpu);
    cudaGetSymbolAddress((void**)&Wpm, g_Wpm);

    cudaFuncSetAttribute(attn_kernel<false>, cudaFuncAttributeMaxDynamicSharedMemorySize, ATT_SMEM_BYTES);
    cudaFuncSetAttribute(attn_kernel<true>,  cudaFuncAttributeMaxDynamicSharedMemorySize, ATT_SMEM_BYTES);
    cudaFuncSetAttribute(ffn_kernel,         cudaFuncAttributeMaxDynamicSharedMemorySize, FFN_SMEM_BYTES);

    prep_kernel<<<64, 256>>>(fW1, fW2, uWq, uWk, uWv, uWp, mWq, mWk, mWv, mWp);

    attn_kernel<false><<<NBLK, TPB, ATT_SMEM_BYTES>>>(x, scratch, Tu, Wpu,
        ubq, ubk, ubv, ubp, g1, be1);
    ffn_kernel<<<NBLK, TPB, FFN_SMEM_BYTES>>>(scratch, out, fb1, fb2, g2, be2);
    attn_kernel<true><<<NBLK, TPB, ATT_SMEM_BYTES>>>(out, scratch, Tm, Wpm,
        mbq, mbk, mbv, mbp, g1, be1);
    ffn_kernel<<<NBLK, TPB, FFN_SMEM_BYTES>>>(scratch, out, fb1, fb2, g2, be2);
}

// round 14
// speedup vs baseline: 1.2483x; 1.0254x over previous
#include <cuda_runtime.h>
#include <cuda_bf16.h>
#include <math.h>

#define NTOK (32768*16)          // 524288 tokens
#define TPB  256
#define TOKS 64                  // tokens per tile
#define NT   4                   // tiles per CTA
#define NBLK (NTOK/(TOKS*NT))    // 2048 CTAs

// ---------------- device globals (allocation-free scratch) ----------------
__device__ float g_scratch[(size_t)NTOK * 64];
__device__ __align__(16) __nv_bfloat16 g_W1b[64*256];
__device__ __align__(16) __nv_bfloat16 g_W2b[256*64];
__device__ __align__(16) __nv_bfloat16 g_Tu[64*192];   // [d][h*8+s (+0/64/128 for q/k/v)]
__device__ __align__(16) __nv_bfloat16 g_Tm[64*192];
__device__ __align__(16) __nv_bfloat16 g_Wpu[64*64];
__device__ __align__(16) __nv_bfloat16 g_Wpm[64*64];

// ---------------- PDL ----------------
#define PDL_TRIGGER() asm volatile("griddepcontrol.launch_dependents;" ::: "memory")
#define PDL_WAIT()    asm volatile("griddepcontrol.wait;" ::: "memory")

// ---------------- small helpers ----------------
__device__ __forceinline__ unsigned bf2u(float a, float b) {
    unsigned r;
    asm("cvt.rn.bf16x2.f32 %0, %1, %2;" : "=r"(r) : "f"(b), "f"(a));
    return r;
}
__device__ __forceinline__ unsigned su32(const void* p) {
    return (unsigned)__cvta_generic_to_shared(p);
}
// fast GELU: 0.5z(1+tanh(0.79788456(z + 0.044715 z^3))), HW tanh
__device__ __forceinline__ float gelu_f(float z) {
    float w = z * fmaf(0.035677408136f, z*z, 0.79788456080287f);
    float t;
    asm("tanh.approx.f32 %0, %1;" : "=f"(t) : "f"(w));
    float hz = 0.5f*z;
    return fmaf(hz, t, hz);
}

#define LDSM4(r0,r1,r2,r3,addr) \
    asm volatile("ldmatrix.sync.aligned.m8n8.x4.shared.b16 {%0,%1,%2,%3},[%4];" \
        : "=r"(r0),"=r"(r1),"=r"(r2),"=r"(r3) : "r"(addr))
#define LDSM4T(r0,r1,r2,r3,addr) \
    asm volatile("ldmatrix.sync.aligned.m8n8.x4.trans.shared.b16 {%0,%1,%2,%3},[%4];" \
        : "=r"(r0),"=r"(r1),"=r"(r2),"=r"(r3) : "r"(addr))
#define MMA16816(c0,c1,c2,c3,a0,a1,a2,a3,b0,b1) \
    asm volatile("mma.sync.aligned.m16n8k16.row.col.f32.bf16.bf16.f32 " \
        "{%0,%1,%2,%3},{%4,%5,%6,%7},{%8,%9},{%0,%1,%2,%3};" \
        : "+f"(c0),"+f"(c1),"+f"(c2),"+f"(c3) \
        : "r"(a0),"r"(a1),"r"(a2),"r"(a3),"r"(b0),"r"(b1))
#define MMA16808(c0,c1,c2,c3,a0,a1,b0) \
    asm volatile("mma.sync.aligned.m16n8k8.row.col.f32.bf16.bf16.f32 " \
        "{%0,%1,%2,%3},{%4,%5},{%6},{%0,%1,%2,%3};" \
        : "+f"(c0),"+f"(c1),"+f"(c2),"+f"(c3) \
        : "r"(a0),"r"(a1),"r"(b0))

// ---- LN split into prefetch (LDG only) + commit (shuffle + STS) ----
__device__ __forceinline__ void ln_prefetch(float* xv, const float* __restrict__ xin,
                                            size_t base, int tid) {
    const int t = tid >> 2, qp = tid & 3;
    const float4* x4 = (const float4*)(xin + (base + t)*64) + qp*4;
#pragma unroll
    for (int i = 0; i < 4; i++) {
        float4 v = x4[i];
        xv[4*i]=v.x; xv[4*i+1]=v.y; xv[4*i+2]=v.z; xv[4*i+3]=v.w;
    }
}
__device__ __forceinline__ void ln_commit(const float* xv, char* __restrict__ sA,
                                          int tid, const float* __restrict__ sg) {
    const int t = tid >> 2, qp = tid & 3;
    float s = 0.f, ss = 0.f;
#pragma unroll
    for (int i = 0; i < 16; i++) { s += xv[i]; ss = fmaf(xv[i], xv[i], ss); }
    s  += __shfl_xor_sync(0xffffffffu, s, 1);  ss += __shfl_xor_sync(0xffffffffu, ss, 1);
    s  += __shfl_xor_sync(0xffffffffu, s, 2);  ss += __shfl_xor_sync(0xffffffffu, ss, 2);
    const float mean = s * (1.f/64.f);
    const float var  = ss * (1.f/64.f) - mean*mean;
    const float rstd = rsqrtf(var + 1e-5f);
    const int kb = qp * 16;
#pragma unroll
    for (int c = 0; c < 2; c++) {
        float v[8];
#pragma unroll
        for (int e = 0; e < 8; e++) {
            int k = kb + c*8 + e;
            v[e] = (xv[c*8+e] - mean) * rstd * sg[k] + sg[64+k];
        }
        uint4 q;
        q.x = bf2u(v[0], v[1]); q.y = bf2u(v[2], v[3]);
        q.z = bf2u(v[4], v[5]); q.w = bf2u(v[6], v[7]);
        int ch = qp*2 + c;
        *(uint4*)(sA + t*128 + ((ch ^ (t & 7)) << 4)) = q;
    }
}

// ---------------- prep: fp32 weights -> bf16 (and qkv transpose) ----------------
__global__ void prep_kernel(const float* __restrict__ W1, const float* __restrict__ W2,
                            const float* __restrict__ uWq, const float* __restrict__ uWk,
                            const float* __restrict__ uWv, const float* __restrict__ uWp,
                            const float* __restrict__ mWq, const float* __restrict__ mWk,
                            const float* __restrict__ mWv, const float* __restrict__ mWp)
{
    int i0 = blockIdx.x * blockDim.x + threadIdx.x;
    int stride = gridDim.x * blockDim.x;
    for (int i = i0; i < 16384; i += stride) {
        g_W1b[i] = __float2bfloat16(W1[i]);
        g_W2b[i] = __float2bfloat16(W2[i]);
    }
    for (int i = i0; i < 4096; i += stride) {
        int h = i >> 9, d = (i >> 3) & 63, s = i & 7;
        int c = h*8 + s;
        g_Tu[d*192 + c]       = __float2bfloat16(uWq[i]);
        g_Tu[d*192 + 64 + c]  = __float2bfloat16(uWk[i]);
        g_Tu[d*192 + 128 + c] = __float2bfloat16(uWv[i]);
        g_Tm[d*192 + c]       = __float2bfloat16(mWq[i]);
        g_Tm[d*192 + 64 + c]  = __float2bfloat16(mWk[i]);
        g_Tm[d*192 + 128 + c] = __float2bfloat16(mWv[i]);
        g_Wpu[i] = __float2bfloat16(uWp[i]);
        g_Wpm[i] = __float2bfloat16(mWp[i]);
    }
}

// ==================================================================
// FFN kernel (R8 proven design): out = x + gelu(LN(x)@W1 + b1)@W2 + b2
// ==================================================================
#define FFN_SW1  0
#define FFN_SW2  32768
#define FFN_SA0  65536
#define FFN_SA1  73728
#define FFN_SRED 81920            // 4 groups x 16 x 68 floats = 17408
#define FFN_SB1  99328
#define FFN_SB2  100352
#define FFN_SG   100608
#define FFN_SMEM_BYTES 101120

__global__ void __launch_bounds__(TPB, 2) ffn_kernel(
    const float* __restrict__ xin, float* __restrict__ xout,
    const float* __restrict__ b1, const float* __restrict__ b2,
    const float* __restrict__ g2, const float* __restrict__ be2)
{
    extern __shared__ char smc[];
    float* sb1 = (float*)(smc + FFN_SB1);
    float* sb2 = (float*)(smc + FFN_SB2);
    float* sg  = (float*)(smc + FFN_SG);

    const int tid = threadIdx.x;
    const unsigned sbase = su32(smc);

    PDL_TRIGGER();   // let the next kernel begin staging under our execution

    {
        const uint4* src1 = (const uint4*)g_W1b;
        const uint4* src2 = (const uint4*)g_W2b;
        for (int c = tid; c < 2048; c += TPB) {
            int r1 = c >> 5, c1 = c & 31;
            *(uint4*)(smc + FFN_SW1 + r1*512 + ((c1 ^ (r1 & 7)) << 4)) = src1[c];
            int r2 = c >> 3, c2 = c & 7;
            *(uint4*)(smc + FFN_SW2 + r2*128 + ((c2 ^ (r2 & 7)) << 4)) = src2[c];
        }
    }
    sb1[tid] = b1[tid];
    if (tid < 64) { sb2[tid] = b2[tid]; sg[tid] = g2[tid]; sg[64+tid] = be2[tid]; }
    __syncthreads();

    PDL_WAIT();      // predecessor output (xin) becomes valid past this point

    const int lane = tid & 31, wid = tid >> 5;
    const int gid = lane >> 2, tig = lane & 3;
    const int tw = wid & 3, nh = wid >> 2;
    const int t0 = tw * 16;
    const int jbase = nh * 128;

    const size_t cta0 = (size_t)blockIdx.x * NT * TOKS;

    float xv[16];
    ln_prefetch(xv, xin, cta0, tid);
    ln_commit(xv, smc + FFN_SA0, tid, sg);
    __syncthreads();

    for (int tt = 0; tt < NT; tt++) {
        const size_t base = cta0 + (size_t)tt * TOKS;
        const unsigned curA = sbase + (((tt & 1) == 0) ? FFN_SA0 : FFN_SA1);
        const unsigned nxtOff = (((tt & 1) == 0) ? FFN_SA1 : FFN_SA0);

        float acc[16][4];
#pragma unroll
        for (int m = 0; m < 16; m++)
#pragma unroll
            for (int p = 0; p < 4; p++) acc[m][p] = 0.f;

#pragma unroll
        for (int ks = 0; ks < 4; ks++) {
            const int k0 = ks * 16;
            unsigned a0,a1,a2,a3;
            {
                int ar = t0 + (lane & 15);
                int ac = (k0 >> 3) + (lane >> 4);
                unsigned aaddr = curA + ar*128 + ((ac ^ (ar & 7)) << 4);
                LDSM4(a0,a1,a2,a3, aaddr);
            }
#pragma unroll
            for (int st = 0; st < 8; st++) {
                int n0 = jbase + st * 16;
                unsigned b0,b1r,b2,b3;
                int br = k0 + (lane & 15);
                int bc = (n0 >> 3) + (lane >> 4);
                unsigned baddr = sbase + FFN_SW1 + br*512 + ((bc ^ (br & 7)) << 4);
                LDSM4T(b0,b1r,b2,b3, baddr);
                MMA16816(acc[2*st][0],acc[2*st][1],acc[2*st][2],acc[2*st][3],
                         a0,a1,a2,a3, b0,b1r);
                MMA16816(acc[2*st+1][0],acc[2*st+1][1],acc[2*st+1][2],acc[2*st+1][3],
                         a0,a1,a2,a3, b2,b3);
            }
        }

        unsigned pk[8][4];
#pragma unroll
        for (int m = 0; m < 16; m++) {
            int col = jbase + m*8 + 2*tig;
            float bb0 = sb1[col], bb1 = sb1[col+1];
            float h00 = gelu_f(acc[m][0] + bb0);
            float h01 = gelu_f(acc[m][1] + bb1);
            float h10 = gelu_f(acc[m][2] + bb0);
            float h11 = gelu_f(acc[m][3] + bb1);
            if ((m & 1) == 0) {
                pk[m>>1][0] = bf2u(h00, h01);
                pk[m>>1][1] = bf2u(h10, h11);
            } else {
                pk[m>>1][2] = bf2u(h00, h01);
                pk[m>>1][3] = bf2u(h10, h11);
            }
        }

        if (tt + 1 < NT) ln_prefetch(xv, xin, base + TOKS, tid);

        float acc2[8][4];
#pragma unroll
        for (int m = 0; m < 8; m++)
#pragma unroll
            for (int p = 0; p < 4; p++) acc2[m][p] = 0.f;

#pragma unroll
        for (int ks = 0; ks < 8; ks++) {
            const int br = jbase + ks*16 + (lane & 15);
#pragma unroll
            for (int st = 0; st < 4; st++) {
                int n0 = st * 16;
                unsigned b0,b1r,b2,b3;
                int bc = (n0 >> 3) + (lane >> 4);
                unsigned baddr = sbase + FFN_SW2 + br*128 + ((bc ^ (br & 7)) << 4);
                LDSM4T(b0,b1r,b2,b3, baddr);
                MMA16816(acc2[2*st][0],acc2[2*st][1],acc2[2*st][2],acc2[2*st][3],
                         pk[ks][0],pk[ks][1],pk[ks][2],pk[ks][3], b0,b1r);
                MMA16816(acc2[2*st+1][0],acc2[2*st+1][1],acc2[2*st+1][2],acc2[2*st+1][3],
                         pk[ks][0],pk[ks][1],pk[ks][2],pk[ks][3], b2,b3);
            }
        }

        float* red = (float*)(smc + FFN_SRED) + tw * (16*68);
        const int st_sto = (nh == 1) ? 0 : 4;
        const int st_fin = (nh == 1) ? 4 : 0;
#pragma unroll
        for (int s = 0; s < 4; s++) {
            int st = st_sto + s;
#pragma unroll
            for (int rp = 0; rp < 2; rp++) {
                int row = gid + rp*8;
                *(float2*)(red + row*68 + st*8 + 2*tig) =
                    make_float2(acc2[st][2*rp], acc2[st][2*rp+1]);
            }
        }
        __syncthreads();
#pragma unroll
        for (int s = 0; s < 4; s++) {
            int st = st_fin + s;
            int e = st*8 + 2*tig;
            float bb0 = sb2[e], bb1 = sb2[e+1];
#pragma unroll
            for (int rp = 0; rp < 2; rp++) {
                int row = gid + rp*8;
                float2 r = *(const float2*)(red + row*68 + e);
                float2 x = *(const float2*)(xin + (base + t0 + row)*64 + e);
                float2 o = make_float2(x.x + r.x + acc2[st][2*rp]   + bb0,
                                       x.y + r.y + acc2[st][2*rp+1] + bb1);
                *(float2*)(xout + (base + t0 + row)*64 + e) = o;
            }
        }

        if (tt + 1 < NT) ln_commit(xv, smc + nxtOff, tid, sg);
        __syncthreads();
    }
}

// ==================================================================
// Attention kernel (R13 design): out = x + attn(LN(x))
// ==================================================================
#define ATT_ST    0
#define ATT_SWP   24576
#define ATT_SA0   32768
#define ATT_SA1   40960
#define ATT_SOB   49152
#define ATT_SQKV  57344
#define ATT_SBQKV 81920
#define ATT_SBP   82688
#define ATT_SG    82944
#define ATT_SMEM_BYTES 83456

template <bool CAUSAL>
__global__ void __launch_bounds__(TPB, 2) attn_kernel(
    const float* __restrict__ xin, float* __restrict__ xout,
    const __nv_bfloat16* __restrict__ Tqkv, const __nv_bfloat16* __restrict__ Wpb,
    const float* __restrict__ bq, const float* __restrict__ bk,
    const float* __restrict__ bv, const float* __restrict__ bp,
    const float* __restrict__ g1, const float* __restrict__ be1)
{
    extern __shared__ char smc[];
    float* sbqkv = (float*)(smc + ATT_SBQKV);
    float* sbp   = (float*)(smc + ATT_SBP);
    float* sg    = (float*)(smc + ATT_SG);

    const int tid = threadIdx.x;
    const unsigned sbase = su32(smc);

    PDL_TRIGGER();   // let the next kernel begin staging under our execution

    {
        const uint4* srcT = (const uint4*)Tqkv;   // 64 rows x 24 chunks
        for (int c = tid; c < 1536; c += TPB) {
            int r = c / 24, ch = c % 24;
            *(uint4*)(smc + ATT_ST + r*384 + ((ch ^ (r & 7)) << 4)) = srcT[c];
        }
        const uint4* srcP = (const uint4*)Wpb;
        for (int c = tid; c < 512; c += TPB) {
            int r = c >> 3, ch = c & 7;
            *(uint4*)(smc + ATT_SWP + r*128 + ((ch ^ (r & 7)) << 4)) = srcP[c];
        }
    }
    if (tid < 192) sbqkv[tid] = (tid < 64) ? bq[tid] : (tid < 128 ? bk[tid-64] : bv[tid-128]);
    if (tid < 64)  sbp[tid] = bp[tid];
    if (tid < 128) sg[tid] = (tid < 64) ? g1[tid] : be1[tid-64];
    __syncthreads();

    PDL_WAIT();      // predecessor output (xin) becomes valid past this point

    const int lane = tid & 31, wid = tid >> 5;
    const int gid = lane >> 2, tig = lane & 3;
    const int tw = wid & 3, nh = wid >> 2;    // phase-3 mapping
    const int t0 = tw * 16;
    const int tg = wid & 1, cg = wid >> 1;    // phase-1 mapping: 32t x 48c
    const int tb0 = tg * 32;
    // phase-2 mapping: warp owns batch pb, 4 consecutive heads hb..hb+3
    const int pb = wid >> 1;
    const int hb = (wid & 1) * 4;

    const size_t cta0 = (size_t)blockIdx.x * NT * TOKS;

    float xv[16];
    ln_prefetch(xv, xin, cta0, tid);
    ln_commit(xv, smc + ATT_SA0, tid, sg);
    __syncthreads();

    for (int tt = 0; tt < NT; tt++) {
        const size_t base = cta0 + (size_t)tt * TOKS;
        const unsigned curA = sbase + (((tt & 1) == 0) ? ATT_SA0 : ATT_SA1);
        const unsigned nxtOff = (((tt & 1) == 0) ? ATT_SA1 : ATT_SA0);

        // ---------- phase 1: QKV = A @ T + b ; warp = 32t x 48c ----------
        {
            float acc[2][6][4];
#pragma unroll
            for (int mi = 0; mi < 2; mi++)
#pragma unroll
                for (int m = 0; m < 6; m++)
#pragma unroll
                    for (int p = 0; p < 4; p++) acc[mi][m][p] = 0.f;

#pragma unroll
            for (int ks = 0; ks < 4; ks++) {
                const int k0 = ks * 16;
                unsigned aA[2][4];
#pragma unroll
                for (int mi = 0; mi < 2; mi++) {
                    int ar = tb0 + mi*16 + (lane & 15);
                    int ac = (k0 >> 3) + (lane >> 4);
                    unsigned aaddr = curA + ar*128 + ((ac ^ (ar & 7)) << 4);
                    LDSM4(aA[mi][0], aA[mi][1], aA[mi][2], aA[mi][3], aaddr);
                }
#pragma unroll
                for (int st = 0; st < 3; st++) {
                    int n0 = cg*48 + st * 16;
                    unsigned b0,b1r,b2,b3;
                    int br = k0 + (lane & 15);
                    int bc = (n0 >> 3) + (lane >> 4);
                    unsigned baddr = sbase + ATT_ST + br*384 + ((bc ^ (br & 7)) << 4);
                    LDSM4T(b0,b1r,b2,b3, baddr);
#pragma unroll
                    for (int mi = 0; mi < 2; mi++) {
                        MMA16816(acc[mi][2*st][0],acc[mi][2*st][1],acc[mi][2*st][2],acc[mi][2*st][3],
                                 aA[mi][0],aA[mi][1],aA[mi][2],aA[mi][3], b0,b1r);
                        MMA16816(acc[mi][2*st+1][0],acc[mi][2*st+1][1],acc[mi][2*st+1][2],acc[mi][2*st+1][3],
                                 aA[mi][0],aA[mi][1],aA[mi][2],aA[mi][3], b2,b3);
                    }
                }
            }

            if (tt + 1 < NT) ln_prefetch(xv, xin, base + TOKS, tid);

#pragma unroll
            for (int mi = 0; mi < 2; mi++)
#pragma unroll
                for (int nf = 0; nf < 6; nf++) {
                    int cc = cg*48 + nf*8;
                    int sec = cc >> 6;               // 0=q 1=k 2=v
                    int h = (cc >> 3) & 7;
                    int c = cc + 2*tig;
                    int b_loc = tg*2 + mi;
                    float bb0 = sbqkv[c], bb1 = sbqkv[c+1];
                    float scale = (sec == 0) ? 0.35355339059327373f : 1.f;
                    float v00 = (acc[mi][nf][0] + bb0) * scale, v01 = (acc[mi][nf][1] + bb1) * scale;
                    float v10 = (acc[mi][nf][2] + bb0) * scale, v11 = (acc[mi][nf][3] + bb1) * scale;
                    unsigned tb = ATT_SQKV + sec*8192 + (b_loc*8 + h)*256 + tig*4;
                    *(unsigned*)(smc + tb + gid*16)     = bf2u(v00, v01);
                    *(unsigned*)(smc + tb + (gid+8)*16) = bf2u(v10, v11);
                }
        }
        __syncthreads();

        // ---------- phase 2: MMA attention core (paired ldmatrix.x4) ----------
        {
#pragma unroll
            for (int ii = 0; ii < 2; ii++) {
                const int h0 = hb + 2*ii;
                const unsigned taddr = sbase + ATT_SQKV + (pb*8 + h0)*256
                                       + (lane >> 4)*256 + (lane & 15)*16;
                unsigned q0,q1,q2,q3, k0,k1,k2,k3, v0,v1,v2,v3;
                LDSM4 (q0,q1,q2,q3, taddr);           // Q tiles h0, h0+1
                LDSM4 (k0,k1,k2,k3, taddr + 8192);    // K
                LDSM4T(v0,v1,v2,v3, taddr + 16384);   // V

#pragma unroll
                for (int j = 0; j < 2; j++) {
                    const int h = h0 + j;
                    unsigned qa0 = j ? q2 : q0, qa1 = j ? q3 : q1;
                    unsigned kb0 = j ? k2 : k0, kb1 = j ? k3 : k1;
                    unsigned vb0 = j ? v2 : v0, vb1 = j ? v3 : v1;

                    float s0=0,s1=0,s2=0,s3=0,s4=0,s5=0,s6=0,s7=0;
                    MMA16808(s0,s1,s2,s3, qa0,qa1, kb0);   // u = 2tig,2tig+1
                    MMA16808(s4,s5,s6,s7, qa0,qa1, kb1);   // u = 2tig+8,2tig+9

                    if (CAUSAL) {
                        const int u0 = 2*tig, u1 = 2*tig+1, u2 = 2*tig+8, u3 = 2*tig+9;
                        if (u0 > gid)   s0 = -1e30f;
                        if (u1 > gid)   s1 = -1e30f;
                        if (u2 > gid)   s4 = -1e30f;
                        if (u3 > gid)   s5 = -1e30f;
                        if (u0 > gid+8) s2 = -1e30f;
                        if (u1 > gid+8) s3 = -1e30f;
                        if (u2 > gid+8) s6 = -1e30f;
                        if (u3 > gid+8) s7 = -1e30f;
                    }
                    float e0 = __expf(s0), e1 = __expf(s1);
                    float e4 = __expf(s4), e5 = __expf(s5);
                    float e2 = __expf(s2), e3 = __expf(s3);
                    float e6 = __expf(s6), e7 = __expf(s7);
                    float slo = e0+e1+e4+e5, shi = e2+e3+e6+e7;
                    slo += __shfl_xor_sync(0xffffffffu, slo, 1);
                    slo += __shfl_xor_sync(0xffffffffu, slo, 2);
                    shi += __shfl_xor_sync(0xffffffffu, shi, 1);
                    shi += __shfl_xor_sync(0xffffffffu, shi, 2);
                    const float ilo = 1.f/slo, ihi = 1.f/shi;

                    unsigned p0 = bf2u(e0, e1);
                    unsigned p1 = bf2u(e2, e3);
                    unsigned p2 = bf2u(e4, e5);
                    unsigned p3 = bf2u(e6, e7);

                    float o0=0,o1=0,o2=0,o3=0;
                    MMA16816(o0,o1,o2,o3, p0,p1,p2,p3, vb0,vb1);
                    o0 *= ilo; o1 *= ilo; o2 *= ihi; o3 *= ihi;

                    const int tA = pb*16 + gid, tB = tA + 8;
                    const int c = h*8 + 2*tig;
                    unsigned offA = ATT_SOB + tA*128 + (((c>>3) ^ (tA & 7)) << 4) + ((c & 7) << 1);
                    unsigned offB = ATT_SOB + tB*128 + (((c>>3) ^ (tB & 7)) << 4) + ((c & 7) << 1);
                    *(unsigned*)(smc + offA) = bf2u(o0, o1);
                    *(unsigned*)(smc + offB) = bf2u(o2, o3);
                }
            }
        }
        __syncthreads();

        // ---------- phase 3: out = x + O @ Wp + bp ; warp = 16t x 32e ----------
        {
            const int ebase = nh * 32;
            float acc[4][4];
#pragma unroll
            for (int m = 0; m < 4; m++)
#pragma unroll
                for (int p = 0; p < 4; p++) acc[m][p] = 0.f;

#pragma unroll
            for (int ks = 0; ks < 4; ks++) {
                const int k0 = ks * 16;
                unsigned a0,a1,a2,a3;
                {
                    int ar = t0 + (lane & 15);
                    int ac = (k0 >> 3) + (lane >> 4);
                    unsigned aaddr = sbase + ATT_SOB + ar*128 + ((ac ^ (ar & 7)) << 4);
                    LDSM4(a0,a1,a2,a3, aaddr);
                }
#pragma unroll
                for (int st = 0; st < 2; st++) {
                    int n0 = ebase + st * 16;
                    unsigned b0,b1r,b2,b3;
                    int br = k0 + (lane & 15);
                    int bc = (n0 >> 3) + (lane >> 4);
                    unsigned baddr = sbase + ATT_SWP + br*128 + ((bc ^ (br & 7)) << 4);
                    LDSM4T(b0,b1r,b2,b3, baddr);
                    MMA16816(acc[2*st][0],acc[2*st][1],acc[2*st][2],acc[2*st][3],
                             a0,a1,a2,a3, b0,b1r);
                    MMA16816(acc[2*st+1][0],acc[2*st+1][1],acc[2*st+1][2],acc[2*st+1][3],
                             a0,a1,a2,a3, b2,b3);
                }
            }
            const int r0 = t0 + gid, r1 = t0 + gid + 8;
#pragma unroll
            for (int m = 0; m < 4; m++) {
                int e = ebase + m*8 + 2*tig;
                float bb0 = sbp[e], bb1 = sbp[e+1];
                float2 x0 = *(const float2*)(xin + (base + r0)*64 + e);
                float2 x1 = *(const float2*)(xin + (base + r1)*64 + e);
                float2 o0 = make_float2(x0.x + acc[m][0] + bb0, x0.y + acc[m][1] + bb1);
                float2 o1 = make_float2(x1.x + acc[m][2] + bb0, x1.y + acc[m][3] + bb1);
                *(float2*)(xout + (base + r0)*64 + e) = o0;
                *(float2*)(xout + (base + r1)*64 + e) = o1;
            }
        }

        if (tt + 1 < NT) ln_commit(xv, smc + nxtOff, tid, sg);
        __syncthreads();
    }
}

// ==================================================================
// launch: prep -> attn(u) -> ffn -> attn(m, causal) -> ffn  (PDL-chained)
// ==================================================================
template <typename K, typename... Args>
static void launch_pdl(K kernel, int smem, Args... args) {
    cudaLaunchConfig_t cfg = {};
    cfg.gridDim = dim3(NBLK, 1, 1);
    cfg.blockDim = dim3(TPB, 1, 1);
    cfg.dynamicSmemBytes = (size_t)smem;
    cfg.stream = 0;
    cudaLaunchAttribute attr[1];
    attr[0].id = cudaLaunchAttributeProgrammaticStreamSerialization;
    attr[0].val.programmaticStreamSerializationAllowed = 1;
    cfg.attrs = attr;
    cfg.numAttrs = 1;
    cudaLaunchKernelEx(&cfg, kernel, args...);
}

extern "C" void kernel_launch(void* const* d_in, const int* in_sizes, int n_in,
                              void* d_out, int out_size)
{
    (void)in_sizes; (void)n_in; (void)out_size;
    const float* x   = (const float*)d_in[0];
    const float* uWq = (const float*)d_in[1];  const float* ubq = (const float*)d_in[2];
    const float* uWk = (const float*)d_in[3];  const float* ubk = (const float*)d_in[4];
    const float* uWv = (const float*)d_in[5];  const float* ubv = (const float*)d_in[6];
    const float* uWp = (const float*)d_in[7];  const float* ubp = (const float*)d_in[8];
    const float* mWq = (const float*)d_in[9];  const float* mbq = (const float*)d_in[10];
    const float* mWk = (const float*)d_in[11]; const float* mbk = (const float*)d_in[12];
    const float* mWv = (const float*)d_in[13]; const float* mbv = (const float*)d_in[14];
    const float* mWp = (const float*)d_in[15]; const float* mbp = (const float*)d_in[16];
    const float* fW1 = (const float*)d_in[17]; const float* fb1 = (const float*)d_in[18];
    const float* fW2 = (const float*)d_in[19]; const float* fb2 = (const float*)d_in[20];
    const float* g1  = (const float*)d_in[21]; const float* be1 = (const float*)d_in[22];
    const float* g2  = (const float*)d_in[23]; const float* be2 = (const float*)d_in[24];
    float* out = (float*)d_out;

    float* scratch = nullptr;
    cudaGetSymbolAddress((void**)&scratch, g_scratch);
    __nv_bfloat16 *Tu = nullptr, *Tm = nullptr, *Wpu = nullptr, *Wpm = nullptr;
    cudaGetSymbolAddress((void**)&Tu, g_Tu);
    cudaGetSymbolAddress((void**)&Tm, g_Tm);
    cudaGetSymbolAddress((void**)&Wpu, g_Wpu);
    cudaGetSymbolAddress((void**)&Wpm, g_Wpm);

    cudaFuncSetAttribute(attn_kernel<false>, cudaFuncAttributeMaxDynamicSharedMemorySize, ATT_SMEM_BYTES);
    cudaFuncSetAttribute(attn_kernel<true>,  cudaFuncAttributeMaxDynamicSharedMemorySize, ATT_SMEM_BYTES);
    cudaFuncSetAttribute(ffn_kernel,         cudaFuncAttributeMaxDynamicSharedMemorySize, FFN_SMEM_BYTES);

    // prep has no early-launch trigger: attn(u) starts only after prep completes,
    // so all g_* weight reads in later kernels are transitively ordered after prep.
    prep_kernel<<<64, 256>>>(fW1, fW2, uWq, uWk, uWv, uWp, mWq, mWk, mWv, mWp);

    launch_pdl(attn_kernel<false>, ATT_SMEM_BYTES,
               x, scratch, (const __nv_bfloat16*)Tu, (const __nv_bfloat16*)Wpu,
               ubq, ubk, ubv, ubp, g1, be1);
    launch_pdl(ffn_kernel, FFN_SMEM_BYTES,
               (const float*)scratch, out, fb1, fb2, g2, be2);
    launch_pdl(attn_kernel<true>, ATT_SMEM_BYTES,
               (const float*)out, scratch, (const __nv_bfloat16*)Tm, (const __nv_bfloat16*)Wpm,
               mbq, mbk, mbv, mbp, g1, be1);
    launch_pdl(ffn_kernel, FFN_SMEM_BYTES,
               (const float*)scratch, out, fb1, fb2, g2, be2);
}

// round 16
// speedup vs baseline: 1.2524x; 1.0032x over previous
#include <cuda_runtime.h>
#include <cuda_bf16.h>
#include <math.h>

#define NTOK (32768*16)          // 524288 tokens
#define TPB  256
#define TOKS 64                  // tokens per tile
#define NT   4                   // tiles per CTA
#define NBLK (NTOK/(TOKS*NT))    // 2048 CTAs

// ---------------- device globals (allocation-free scratch) ----------------
// all weight images are PRE-SWIZZLED (XOR-128B) so kernel staging is a flat copy
__device__ float g_scratch[(size_t)NTOK * 64];
__device__ __align__(16) __nv_bfloat16 g_W1s[64*256];   // [k][j] 512B rows, swizzled
__device__ __align__(16) __nv_bfloat16 g_W2s[256*64];   // [j][e] 128B rows, swizzled
__device__ __align__(16) __nv_bfloat16 g_TuS[64*192];   // [d][c] 384B rows, swizzled
__device__ __align__(16) __nv_bfloat16 g_TmS[64*192];
__device__ __align__(16) __nv_bfloat16 g_WpuS[64*64];   // [c][e] 128B rows, swizzled
__device__ __align__(16) __nv_bfloat16 g_WpmS[64*64];

// ---------------- PDL ----------------
#define PDL_TRIGGER() asm volatile("griddepcontrol.launch_dependents;" ::: "memory")
#define PDL_WAIT()    asm volatile("griddepcontrol.wait;" ::: "memory")

// ---------------- small helpers ----------------
__device__ __forceinline__ unsigned bf2u(float a, float b) {
    unsigned r;
    asm("cvt.rn.bf16x2.f32 %0, %1, %2;" : "=r"(r) : "f"(b), "f"(a));
    return r;
}
__device__ __forceinline__ unsigned su32(const void* p) {
    return (unsigned)__cvta_generic_to_shared(p);
}
// fast GELU: 0.5z(1+tanh(0.79788456(z + 0.044715 z^3))), HW tanh
__device__ __forceinline__ float gelu_f(float z) {
    float w = z * fmaf(0.035677408136f, z*z, 0.79788456080287f);
    float t;
    asm("tanh.approx.f32 %0, %1;" : "=f"(t) : "f"(w));
    float hz = 0.5f*z;
    return fmaf(hz, t, hz);
}

#define LDSM4(r0,r1,r2,r3,addr) \
    asm volatile("ldmatrix.sync.aligned.m8n8.x4.shared.b16 {%0,%1,%2,%3},[%4];" \
        : "=r"(r0),"=r"(r1),"=r"(r2),"=r"(r3) : "r"(addr))
#define LDSM4T(r0,r1,r2,r3,addr) \
    asm volatile("ldmatrix.sync.aligned.m8n8.x4.trans.shared.b16 {%0,%1,%2,%3},[%4];" \
        : "=r"(r0),"=r"(r1),"=r"(r2),"=r"(r3) : "r"(addr))
#define MMA16816(c0,c1,c2,c3,a0,a1,a2,a3,b0,b1) \
    asm volatile("mma.sync.aligned.m16n8k16.row.col.f32.bf16.bf16.f32 " \
        "{%0,%1,%2,%3},{%4,%5,%6,%7},{%8,%9},{%0,%1,%2,%3};" \
        : "+f"(c0),"+f"(c1),"+f"(c2),"+f"(c3) \
        : "r"(a0),"r"(a1),"r"(a2),"r"(a3),"r"(b0),"r"(b1))
#define MMA16808(c0,c1,c2,c3,a0,a1,b0) \
    asm volatile("mma.sync.aligned.m16n8k8.row.col.f32.bf16.bf16.f32 " \
        "{%0,%1,%2,%3},{%4,%5},{%6},{%0,%1,%2,%3};" \
        : "+f"(c0),"+f"(c1),"+f"(c2),"+f"(c3) \
        : "r"(a0),"r"(a1),"r"(b0))

// ---- LN split into prefetch (LDG only) + commit (shuffle + STS) ----
__device__ __forceinline__ void ln_prefetch(float* xv, const float* __restrict__ xin,
                                            size_t base, int tid) {
    const int t = tid >> 2, qp = tid & 3;
    const float4* x4 = (const float4*)(xin + (base + t)*64) + qp*4;
#pragma unroll
    for (int i = 0; i < 4; i++) {
        float4 v = x4[i];
        xv[4*i]=v.x; xv[4*i+1]=v.y; xv[4*i+2]=v.z; xv[4*i+3]=v.w;
    }
}
__device__ __forceinline__ void ln_commit(const float* xv, char* __restrict__ sA,
                                          int tid, const float* __restrict__ sg) {
    const int t = tid >> 2, qp = tid & 3;
    float s = 0.f, ss = 0.f;
#pragma unroll
    for (int i = 0; i < 16; i++) { s += xv[i]; ss = fmaf(xv[i], xv[i], ss); }
    s  += __shfl_xor_sync(0xffffffffu, s, 1);  ss += __shfl_xor_sync(0xffffffffu, ss, 1);
    s  += __shfl_xor_sync(0xffffffffu, s, 2);  ss += __shfl_xor_sync(0xffffffffu, ss, 2);
    const float mean = s * (1.f/64.f);
    const float var  = ss * (1.f/64.f) - mean*mean;
    const float rstd = rsqrtf(var + 1e-5f);
    const int kb = qp * 16;
#pragma unroll
    for (int c = 0; c < 2; c++) {
        float v[8];
#pragma unroll
        for (int e = 0; e < 8; e++) {
            int k = kb + c*8 + e;
            v[e] = (xv[c*8+e] - mean) * rstd * sg[k] + sg[64+k];
        }
        uint4 q;
        q.x = bf2u(v[0], v[1]); q.y = bf2u(v[2], v[3]);
        q.z = bf2u(v[4], v[5]); q.w = bf2u(v[6], v[7]);
        int ch = qp*2 + c;
        *(uint4*)(sA + t*128 + ((ch ^ (t & 7)) << 4)) = q;
    }
}

// ---------------- prep: fp32 weights -> bf16, SWIZZLE BAKED ----------------
__global__ void prep_kernel(const float* __restrict__ W1, const float* __restrict__ W2,
                            const float* __restrict__ uWq, const float* __restrict__ uWk,
                            const float* __restrict__ uWv, const float* __restrict__ uWp,
                            const float* __restrict__ mWq, const float* __restrict__ mWk,
                            const float* __restrict__ mWv, const float* __restrict__ mWp)
{
    int i0 = blockIdx.x * blockDim.x + threadIdx.x;
    int stride = gridDim.x * blockDim.x;
    for (int i = i0; i < 16384; i += stride) {
        // W1[k][j]: smem idx = k*256 + ((j>>3 ^ (k&7))<<3) + (j&7)
        int k = i >> 8, j = i & 255;
        g_W1s[k*256 + ((((j>>3) ^ (k & 7))) << 3) + (j & 7)] = __float2bfloat16(W1[i]);
        // W2[jj][e]: smem idx = jj*64 + ((e>>3 ^ (jj&7))<<3) + (e&7)
        int jj = i >> 6, e = i & 63;
        g_W2s[jj*64 + ((((e>>3) ^ (jj & 7))) << 3) + (e & 7)] = __float2bfloat16(W2[i]);
    }
    for (int i = i0; i < 4096; i += stride) {
        int h = i >> 9, d = (i >> 3) & 63, s = i & 7;
        int c = h*8 + s;
        // Tqkv[d][cc], cc = sec*64 + c: idx = d*192 + ((cc>>3 ^ (d&7))<<3) + (cc&7)
#pragma unroll
        for (int sec = 0; sec < 3; sec++) {
            int cc = sec*64 + c;
            int idx = d*192 + ((((cc>>3) ^ (d & 7))) << 3) + (cc & 7);
            g_TuS[idx] = __float2bfloat16(sec == 0 ? uWq[i] : (sec == 1 ? uWk[i] : uWv[i]));
            g_TmS[idx] = __float2bfloat16(sec == 0 ? mWq[i] : (sec == 1 ? mWk[i] : mWv[i]));
        }
        // Wp[pc][pe]: idx = pc*64 + ((pe>>3 ^ (pc&7))<<3) + (pe&7)
        int pc = i >> 6, pe = i & 63;
        int idp = pc*64 + ((((pe>>3) ^ (pc & 7))) << 3) + (pe & 7);
        g_WpuS[idp] = __float2bfloat16(uWp[i]);
        g_WpmS[idp] = __float2bfloat16(mWp[i]);
    }
}

// ==================================================================
// FFN kernel (R8 proven design): out = x + gelu(LN(x)@W1 + b1)@W2 + b2
// ==================================================================
#define FFN_SW1  0
#define FFN_SW2  32768
#define FFN_SA0  65536
#define FFN_SA1  73728
#define FFN_SRED 81920            // 4 groups x 16 x 68 floats = 17408
#define FFN_SB1  99328
#define FFN_SB2  100352
#define FFN_SG   100608
#define FFN_SMEM_BYTES 101120

__global__ void __launch_bounds__(TPB, 2) ffn_kernel(
    const float* __restrict__ xin, float* __restrict__ xout,
    const float* __restrict__ b1, const float* __restrict__ b2,
    const float* __restrict__ g2, const float* __restrict__ be2)
{
    extern __shared__ char smc[];
    float* sb1 = (float*)(smc + FFN_SB1);
    float* sb2 = (float*)(smc + FFN_SB2);
    float* sg  = (float*)(smc + FFN_SG);

    const int tid = threadIdx.x;
    const unsigned sbase = su32(smc);

    PDL_TRIGGER();   // let the next kernel begin staging under our execution

    // flat staging — swizzle baked in global images
    {
        const uint4* s1 = (const uint4*)g_W1s;
        const uint4* s2 = (const uint4*)g_W2s;
        uint4* d1 = (uint4*)(smc + FFN_SW1);
        uint4* d2 = (uint4*)(smc + FFN_SW2);
        for (int c = tid; c < 2048; c += TPB) { d1[c] = s1[c]; d2[c] = s2[c]; }
    }
    sb1[tid] = b1[tid];
    if (tid < 64) { sb2[tid] = b2[tid]; sg[tid] = g2[tid]; sg[64+tid] = be2[tid]; }
    __syncthreads();

    PDL_WAIT();      // predecessor output (xin) becomes valid past this point

    const int lane = tid & 31, wid = tid >> 5;
    const int gid = lane >> 2, tig = lane & 3;
    const int tw = wid & 3, nh = wid >> 2;
    const int t0 = tw * 16;
    const int jbase = nh * 128;

    const size_t cta0 = (size_t)blockIdx.x * NT * TOKS;

    float xv[16];
    ln_prefetch(xv, xin, cta0, tid);
    ln_commit(xv, smc + FFN_SA0, tid, sg);
    __syncthreads();

    for (int tt = 0; tt < NT; tt++) {
        const size_t base = cta0 + (size_t)tt * TOKS;
        const unsigned curA = sbase + (((tt & 1) == 0) ? FFN_SA0 : FFN_SA1);
        const unsigned nxtOff = (((tt & 1) == 0) ? FFN_SA1 : FFN_SA0);

        float acc[16][4];
#pragma unroll
        for (int m = 0; m < 16; m++)
#pragma unroll
            for (int p = 0; p < 4; p++) acc[m][p] = 0.f;

#pragma unroll
        for (int ks = 0; ks < 4; ks++) {
            const int k0 = ks * 16;
            unsigned a0,a1,a2,a3;
            {
                int ar = t0 + (lane & 15);
                int ac = (k0 >> 3) + (lane >> 4);
                unsigned aaddr = curA + ar*128 + ((ac ^ (ar & 7)) << 4);
                LDSM4(a0,a1,a2,a3, aaddr);
            }
#pragma unroll
            for (int st = 0; st < 8; st++) {
                int n0 = jbase + st * 16;
                unsigned b0,b1r,b2,b3;
                int br = k0 + (lane & 15);
                int bc = (n0 >> 3) + (lane >> 4);
                unsigned baddr = sbase + FFN_SW1 + br*512 + ((bc ^ (br & 7)) << 4);
                LDSM4T(b0,b1r,b2,b3, baddr);
                MMA16816(acc[2*st][0],acc[2*st][1],acc[2*st][2],acc[2*st][3],
                         a0,a1,a2,a3, b0,b1r);
                MMA16816(acc[2*st+1][0],acc[2*st+1][1],acc[2*st+1][2],acc[2*st+1][3],
                         a0,a1,a2,a3, b2,b3);
            }
        }

        unsigned pk[8][4];
#pragma unroll
        for (int m = 0; m < 16; m++) {
            int col = jbase + m*8 + 2*tig;
            float bb0 = sb1[col], bb1 = sb1[col+1];
            float h00 = gelu_f(acc[m][0] + bb0);
            float h01 = gelu_f(acc[m][1] + bb1);
            float h10 = gelu_f(acc[m][2] + bb0);
            float h11 = gelu_f(acc[m][3] + bb1);
            if ((m & 1) == 0) {
                pk[m>>1][0] = bf2u(h00, h01);
                pk[m>>1][1] = bf2u(h10, h11);
            } else {
                pk[m>>1][2] = bf2u(h00, h01);
                pk[m>>1][3] = bf2u(h10, h11);
            }
        }

        if (tt + 1 < NT) ln_prefetch(xv, xin, base + TOKS, tid);

        float acc2[8][4];
#pragma unroll
        for (int m = 0; m < 8; m++)
#pragma unroll
            for (int p = 0; p < 4; p++) acc2[m][p] = 0.f;

#pragma unroll
        for (int ks = 0; ks < 8; ks++) {
            const int br = jbase + ks*16 + (lane & 15);
#pragma unroll
            for (int st = 0; st < 4; st++) {
                int n0 = st * 16;
                unsigned b0,b1r,b2,b3;
                int bc = (n0 >> 3) + (lane >> 4);
                unsigned baddr = sbase + FFN_SW2 + br*128 + ((bc ^ (br & 7)) << 4);
                LDSM4T(b0,b1r,b2,b3, baddr);
                MMA16816(acc2[2*st][0],acc2[2*st][1],acc2[2*st][2],acc2[2*st][3],
                         pk[ks][0],pk[ks][1],pk[ks][2],pk[ks][3], b0,b1r);
                MMA16816(acc2[2*st+1][0],acc2[2*st+1][1],acc2[2*st+1][2],acc2[2*st+1][3],
                         pk[ks][0],pk[ks][1],pk[ks][2],pk[ks][3], b2,b3);
            }
        }

        float* red = (float*)(smc + FFN_SRED) + tw * (16*68);
        const int st_sto = (nh == 1) ? 0 : 4;
        const int st_fin = (nh == 1) ? 4 : 0;
#pragma unroll
        for (int s = 0; s < 4; s++) {
            int st = st_sto + s;
#pragma unroll
            for (int rp = 0; rp < 2; rp++) {
                int row = gid + rp*8;
                *(float2*)(red + row*68 + st*8 + 2*tig) =
                    make_float2(acc2[st][2*rp], acc2[st][2*rp+1]);
            }
        }
        __syncthreads();
#pragma unroll
        for (int s = 0; s < 4; s++) {
            int st = st_fin + s;
            int e = st*8 + 2*tig;
            float bb0 = sb2[e], bb1 = sb2[e+1];
#pragma unroll
            for (int rp = 0; rp < 2; rp++) {
                int row = gid + rp*8;
                float2 r = *(const float2*)(red + row*68 + e);
                float2 x = *(const float2*)(xin + (base + t0 + row)*64 + e);
                float2 o = make_float2(x.x + r.x + acc2[st][2*rp]   + bb0,
                                       x.y + r.y + acc2[st][2*rp+1] + bb1);
                *(float2*)(xout + (base + t0 + row)*64 + e) = o;
            }
        }

        if (tt + 1 < NT) ln_commit(xv, smc + nxtOff, tid, sg);
        __syncthreads();
    }
}

// ==================================================================
// Attention kernel (R14 design, flat staging): out = x + attn(LN(x))
// ==================================================================
#define ATT_ST    0
#define ATT_SWP   24576
#define ATT_SA0   32768
#define ATT_SA1   40960
#define ATT_SOB   49152
#define ATT_SQKV  57344
#define ATT_SBQKV 81920
#define ATT_SBP   82688
#define ATT_SG    82944
#define ATT_SMEM_BYTES 83456

template <bool CAUSAL>
__global__ void __launch_bounds__(TPB, 2) attn_kernel(
    const float* __restrict__ xin, float* __restrict__ xout,
    const __nv_bfloat16* __restrict__ Tqkv, const __nv_bfloat16* __restrict__ Wpb,
    const float* __restrict__ bq, const float* __restrict__ bk,
    const float* __restrict__ bv, const float* __restrict__ bp,
    const float* __restrict__ g1, const float* __restrict__ be1)
{
    extern __shared__ char smc[];
    float* sbqkv = (float*)(smc + ATT_SBQKV);
    float* sbp   = (float*)(smc + ATT_SBP);
    float* sg    = (float*)(smc + ATT_SG);

    const int tid = threadIdx.x;
    const unsigned sbase = su32(smc);

    PDL_TRIGGER();   // let the next kernel begin staging under our execution

    // flat staging — swizzle baked in global images
    {
        const uint4* srcT = (const uint4*)Tqkv;
        uint4* dT = (uint4*)(smc + ATT_ST);
        for (int c = tid; c < 1536; c += TPB) dT[c] = srcT[c];
        const uint4* srcP = (const uint4*)Wpb;
        uint4* dP = (uint4*)(smc + ATT_SWP);
        for (int c = tid; c < 512; c += TPB) dP[c] = srcP[c];
    }
    if (tid < 192) sbqkv[tid] = (tid < 64) ? bq[tid] : (tid < 128 ? bk[tid-64] : bv[tid-128]);
    if (tid < 64)  sbp[tid] = bp[tid];
    if (tid < 128) sg[tid] = (tid < 64) ? g1[tid] : be1[tid-64];
    __syncthreads();

    PDL_WAIT();      // predecessor output (xin) becomes valid past this point

    const int lane = tid & 31, wid = tid >> 5;
    const int gid = lane >> 2, tig = lane & 3;
    const int tw = wid & 3, nh = wid >> 2;    // phase-3 mapping
    const int t0 = tw * 16;
    const int tg = wid & 1, cg = wid >> 1;    // phase-1 mapping: 32t x 48c
    const int tb0 = tg * 32;
    const int pb = wid >> 1;                  // phase-2: batch
    const int hb = (wid & 1) * 4;             // phase-2: head base

    const size_t cta0 = (size_t)blockIdx.x * NT * TOKS;

    float xv[16];
    ln_prefetch(xv, xin, cta0, tid);
    ln_commit(xv, smc + ATT_SA0, tid, sg);
    __syncthreads();

    for (int tt = 0; tt < NT; tt++) {
        const size_t base = cta0 + (size_t)tt * TOKS;
        const unsigned curA = sbase + (((tt & 1) == 0) ? ATT_SA0 : ATT_SA1);
        const unsigned nxtOff = (((tt & 1) == 0) ? ATT_SA1 : ATT_SA0);

        // ---------- phase 1: QKV = A @ T + b ; warp = 32t x 48c ----------
        {
            float acc[2][6][4];
#pragma unroll
            for (int mi = 0; mi < 2; mi++)
#pragma unroll
                for (int m = 0; m < 6; m++)
#pragma unroll
                    for (int p = 0; p < 4; p++) acc[mi][m][p] = 0.f;

#pragma unroll
            for (int ks = 0; ks < 4; ks++) {
                const int k0 = ks * 16;
                unsigned aA[2][4];
#pragma unroll
                for (int mi = 0; mi < 2; mi++) {
                    int ar = tb0 + mi*16 + (lane & 15);
                    int ac = (k0 >> 3) + (lane >> 4);
                    unsigned aaddr = curA + ar*128 + ((ac ^ (ar & 7)) << 4);
                    LDSM4(aA[mi][0], aA[mi][1], aA[mi][2], aA[mi][3], aaddr);
                }
#pragma unroll
                for (int st = 0; st < 3; st++) {
                    int n0 = cg*48 + st * 16;
                    unsigned b0,b1r,b2,b3;
                    int br = k0 + (lane & 15);
                    int bc = (n0 >> 3) + (lane >> 4);
                    unsigned baddr = sbase + ATT_ST + br*384 + ((bc ^ (br & 7)) << 4);
                    LDSM4T(b0,b1r,b2,b3, baddr);
#pragma unroll
                    for (int mi = 0; mi < 2; mi++) {
                        MMA16816(acc[mi][2*st][0],acc[mi][2*st][1],acc[mi][2*st][2],acc[mi][2*st][3],
                                 aA[mi][0],aA[mi][1],aA[mi][2],aA[mi][3], b0,b1r);
                        MMA16816(acc[mi][2*st+1][0],acc[mi][2*st+1][1],acc[mi][2*st+1][2],acc[mi][2*st+1][3],
                                 aA[mi][0],aA[mi][1],aA[mi][2],aA[mi][3], b2,b3);
                    }
                }
            }

            if (tt + 1 < NT) ln_prefetch(xv, xin, base + TOKS, tid);

#pragma unroll
            for (int mi = 0; mi < 2; mi++)
#pragma unroll
                for (int nf = 0; nf < 6; nf++) {
                    int cc = cg*48 + nf*8;
                    int sec = cc >> 6;               // 0=q 1=k 2=v
                    int h = (cc >> 3) & 7;
                    int c = cc + 2*tig;
                    int b_loc = tg*2 + mi;
                    float bb0 = sbqkv[c], bb1 = sbqkv[c+1];
                    float scale = (sec == 0) ? 0.35355339059327373f : 1.f;
                    float v00 = (acc[mi][nf][0] + bb0) * scale, v01 = (acc[mi][nf][1] + bb1) * scale;
                    float v10 = (acc[mi][nf][2] + bb0) * scale, v11 = (acc[mi][nf][3] + bb1) * scale;
                    unsigned tb = ATT_SQKV + sec*8192 + (b_loc*8 + h)*256 + tig*4;
                    *(unsigned*)(smc + tb + gid*16)     = bf2u(v00, v01);
                    *(unsigned*)(smc + tb + (gid+8)*16) = bf2u(v10, v11);
                }
        }
        __syncthreads();

        // ---------- phase 2: MMA attention core (paired ldmatrix.x4) ----------
        {
#pragma unroll
            for (int ii = 0; ii < 2; ii++) {
                const int h0 = hb + 2*ii;
                const unsigned taddr = sbase + ATT_SQKV + (pb*8 + h0)*256
                                       + (lane >> 4)*256 + (lane & 15)*16;
                unsigned q0,q1,q2,q3, k0,k1,k2,k3, v0,v1,v2,v3;
                LDSM4 (q0,q1,q2,q3, taddr);           // Q tiles h0, h0+1
                LDSM4 (k0,k1,k2,k3, taddr + 8192);    // K
                LDSM4T(v0,v1,v2,v3, taddr + 16384);   // V

#pragma unroll
                for (int j = 0; j < 2; j++) {
                    const int h = h0 + j;
                    unsigned qa0 = j ? q2 : q0, qa1 = j ? q3 : q1;
                    unsigned kb0 = j ? k2 : k0, kb1 = j ? k3 : k1;
                    unsigned vb0 = j ? v2 : v0, vb1 = j ? v3 : v1;

                    float s0=0,s1=0,s2=0,s3=0,s4=0,s5=0,s6=0,s7=0;
                    MMA16808(s0,s1,s2,s3, qa0,qa1, kb0);   // u = 2tig,2tig+1
                    MMA16808(s4,s5,s6,s7, qa0,qa1, kb1);   // u = 2tig+8,2tig+9

                    if (CAUSAL) {
                        const int u0 = 2*tig, u1 = 2*tig+1, u2 = 2*tig+8, u3 = 2*tig+9;
                        if (u0 > gid)   s0 = -1e30f;
                        if (u1 > gid)   s1 = -1e30f;
                        if (u2 > gid)   s4 = -1e30f;
                        if (u3 > gid)   s5 = -1e30f;
                        if (u0 > gid+8) s2 = -1e30f;
                        if (u1 > gid+8) s3 = -1e30f;
                        if (u2 > gid+8) s6 = -1e30f;
                        if (u3 > gid+8) s7 = -1e30f;
                    }
                    float e0 = __expf(s0), e1 = __expf(s1);
                    float e4 = __expf(s4), e5 = __expf(s5);
                    float e2 = __expf(s2), e3 = __expf(s3);
                    float e6 = __expf(s6), e7 = __expf(s7);
                    float slo = e0+e1+e4+e5, shi = e2+e3+e6+e7;
                    slo += __shfl_xor_sync(0xffffffffu, slo, 1);
                    slo += __shfl_xor_sync(0xffffffffu, slo, 2);
                    shi += __shfl_xor_sync(0xffffffffu, shi, 1);
                    shi += __shfl_xor_sync(0xffffffffu, shi, 2);
                    const float ilo = 1.f/slo, ihi = 1.f/shi;

                    unsigned p0 = bf2u(e0, e1);
                    unsigned p1 = bf2u(e2, e3);
                    unsigned p2 = bf2u(e4, e5);
                    unsigned p3 = bf2u(e6, e7);

                    float o0=0,o1=0,o2=0,o3=0;
                    MMA16816(o0,o1,o2,o3, p0,p1,p2,p3, vb0,vb1);
                    o0 *= ilo; o1 *= ilo; o2 *= ihi; o3 *= ihi;

                    const int tA = pb*16 + gid, tB = tA + 8;
                    const int c = h*8 + 2*tig;
                    unsigned offA = ATT_SOB + tA*128 + (((c>>3) ^ (tA & 7)) << 4) + ((c & 7) << 1);
                    unsigned offB = ATT_SOB + tB*128 + (((c>>3) ^ (tB & 7)) << 4) + ((c & 7) << 1);
                    *(unsigned*)(smc + offA) = bf2u(o0, o1);
                    *(unsigned*)(smc + offB) = bf2u(o2, o3);
                }
            }
        }
        __syncthreads();

        // ---------- phase 3: out = x + O @ Wp + bp ; warp = 16t x 32e ----------
        {
            const int ebase = nh * 32;
            float acc[4][4];
#pragma unroll
            for (int m = 0; m < 4; m++)
#pragma unroll
                for (int p = 0; p < 4; p++) acc[m][p] = 0.f;

#pragma unroll
            for (int ks = 0; ks < 4; ks++) {
                const int k0 = ks * 16;
                unsigned a0,a1,a2,a3;
                {
                    int ar = t0 + (lane & 15);
                    int ac = (k0 >> 3) + (lane >> 4);
                    unsigned aaddr = sbase + ATT_SOB + ar*128 + ((ac ^ (ar & 7)) << 4);
                    LDSM4(a0,a1,a2,a3, aaddr);
                }
#pragma unroll
                for (int st = 0; st < 2; st++) {
                    int n0 = ebase + st * 16;
                    unsigned b0,b1r,b2,b3;
                    int br = k0 + (lane & 15);
                    int bc = (n0 >> 3) + (lane >> 4);
                    unsigned baddr = sbase + ATT_SWP + br*128 + ((bc ^ (br & 7)) << 4);
                    LDSM4T(b0,b1r,b2,b3, baddr);
                    MMA16816(acc[2*st][0],acc[2*st][1],acc[2*st][2],acc[2*st][3],
                             a0,a1,a2,a3, b0,b1r);
                    MMA16816(acc[2*st+1][0],acc[2*st+1][1],acc[2*st+1][2],acc[2*st+1][3],
                             a0,a1,a2,a3, b2,b3);
                }
            }
            const int r0 = t0 + gid, r1 = t0 + gid + 8;
#pragma unroll
            for (int m = 0; m < 4; m++) {
                int e = ebase + m*8 + 2*tig;
                float bb0 = sbp[e], bb1 = sbp[e+1];
                float2 x0 = *(const float2*)(xin + (base + r0)*64 + e);
                float2 x1 = *(const float2*)(xin + (base + r1)*64 + e);
                float2 o0 = make_float2(x0.x + acc[m][0] + bb0, x0.y + acc[m][1] + bb1);
                float2 o1 = make_float2(x1.x + acc[m][2] + bb0, x1.y + acc[m][3] + bb1);
                *(float2*)(xout + (base + r0)*64 + e) = o0;
                *(float2*)(xout + (base + r1)*64 + e) = o1;
            }
        }

        if (tt + 1 < NT) ln_commit(xv, smc + nxtOff, tid, sg);
        __syncthreads();
    }
}

// ==================================================================
// launch: prep -> attn(u) -> ffn -> attn(m, causal) -> ffn  (PDL-chained)
// ==================================================================
template <typename K, typename... Args>
static void launch_pdl(K kernel, int smem, Args... args) {
    cudaLaunchConfig_t cfg = {};
    cfg.gridDim = dim3(NBLK, 1, 1);
    cfg.blockDim = dim3(TPB, 1, 1);
    cfg.dynamicSmemBytes = (size_t)smem;
    cfg.stream = 0;
    cudaLaunchAttribute attr[1];
    attr[0].id = cudaLaunchAttributeProgrammaticStreamSerialization;
    attr[0].val.programmaticStreamSerializationAllowed = 1;
    cfg.attrs = attr;
    cfg.numAttrs = 1;
    cudaLaunchKernelEx(&cfg, kernel, args...);
}

extern "C" void kernel_launch(void* const* d_in, const int* in_sizes, int n_in,
                              void* d_out, int out_size)
{
    (void)in_sizes; (void)n_in; (void)out_size;
    const float* x   = (const float*)d_in[0];
    const float* uWq = (const float*)d_in[1];  const float* ubq = (const float*)d_in[2];
    const float* uWk = (const float*)d_in[3];  const float* ubk = (const float*)d_in[4];
    const float* uWv = (const float*)d_in[5];  const float* ubv = (const float*)d_in[6];
    const float* uWp = (const float*)d_in[7];  const float* ubp = (const float*)d_in[8];
    const float* mWq = (const float*)d_in[9];  const float* mbq = (const float*)d_in[10];
    const float* mWk = (const float*)d_in[11]; const float* mbk = (const float*)d_in[12];
    const float* mWv = (const float*)d_in[13]; const float* mbv = (const float*)d_in[14];
    const float* mWp = (const float*)d_in[15]; const float* mbp = (const float*)d_in[16];
    const float* fW1 = (const float*)d_in[17]; const float* fb1 = (const float*)d_in[18];
    const float* fW2 = (const float*)d_in[19]; const float* fb2 = (const float*)d_in[20];
    const float* g1  = (const float*)d_in[21]; const float* be1 = (const float*)d_in[22];
    const float* g2  = (const float*)d_in[23]; const float* be2 = (const float*)d_in[24];
    float* out = (float*)d_out;

    float* scratch = nullptr;
    cudaGetSymbolAddress((void**)&scratch, g_scratch);
    __nv_bfloat16 *Tu = nullptr, *Tm = nullptr, *Wpu = nullptr, *Wpm = nullptr;
    cudaGetSymbolAddress((void**)&Tu, g_TuS);
    cudaGetSymbolAddress((void**)&Tm, g_TmS);
    cudaGetSymbolAddress((void**)&Wpu, g_WpuS);
    cudaGetSymbolAddress((void**)&Wpm, g_WpmS);

    cudaFuncSetAttribute(attn_kernel<false>, cudaFuncAttributeMaxDynamicSharedMemorySize, ATT_SMEM_BYTES);
    cudaFuncSetAttribute(attn_kernel<true>,  cudaFuncAttributeMaxDynamicSharedMemorySize, ATT_SMEM_BYTES);
    cudaFuncSetAttribute(ffn_kernel,         cudaFuncAttributeMaxDynamicSharedMemorySize, FFN_SMEM_BYTES);

    // prep has no early-launch trigger: attn(u) starts only after prep completes,
    // so all g_* weight reads in later kernels are transitively ordered after prep.
    prep_kernel<<<64, 256>>>(fW1, fW2, uWq, uWk, uWv, uWp, mWq, mWk, mWv, mWp);

    launch_pdl(attn_kernel<false>, ATT_SMEM_BYTES,
               x, scratch, (const __nv_bfloat16*)Tu, (const __nv_bfloat16*)Wpu,
               ubq, ubk, ubv, ubp, g1, be1);
    launch_pdl(ffn_kernel, FFN_SMEM_BYTES,
               (const float*)scratch, out, fb1, fb2, g2, be2);
    launch_pdl(attn_kernel<true>, ATT_SMEM_BYTES,
               (const float*)out, scratch, (const __nv_bfloat16*)Tm, (const __nv_bfloat16*)Wpm,
               mbq, mbk, mbv, mbp, g1, be1);
    launch_pdl(ffn_kernel, FFN_SMEM_BYTES,
               (const float*)scratch, out, fb1, fb2, g2, be2);
}